// round 8
// baseline (speedup 1.0000x reference)
#include <cuda_runtime.h>
#include <cuda_fp16.h>
#include <cstdint>

#define DD 256
#define BB 16
#define NN 2048
#define ROWS (BB*NN)

typedef __half h16;

// ------------------------------------------------------------------ scratch
__device__ float g_W[DD*DD];                 // Wq @ Wk^T
__device__ float g_u[DD];                    // Wk @ bq
__device__ float g_c[ROWS];                  // X . u  (per key row)
__device__ float g_C[(size_t)ROWS*16];       // per (qrow, keytile) correction/norm

__device__ h16 g_Xh[(size_t)ROWS*DD],  g_Xl[(size_t)ROWS*DD];    // X splits (row-major)
__device__ h16 g_Xth[(size_t)BB*DD*NN];                          // X^T (hi only)
__device__ h16 g_Aph[(size_t)ROWS*DD], g_Apl[(size_t)ROWS*DD];   // A' = X@W splits
__device__ h16 g_Ph[(size_t)ROWS*NN];                            // exp(S - m_run) fp16
__device__ h16 g_aggh[(size_t)ROWS*DD], g_aggl[(size_t)ROWS*DD]; // agg splits
__device__ h16 g_Wth[DD*DD], g_Wtl[DD*DD];   // (WqWk^T)^T splits
__device__ h16 g_Woth[DD*DD], g_Wotl[DD*DD]; // Wo^T splits

// ------------------------------------------------------------------ helpers
__device__ __forceinline__ uint32_t smem_u32(const void* p) {
    uint32_t a;
    asm("{ .reg .u64 t; cvta.to.shared.u64 t, %1; cvt.u32.u64 %0, t; }" : "=r"(a) : "l"(p));
    return a;
}
#define CP16(dst, src) \
    asm volatile("cp.async.cg.shared.global [%0], [%1], 16;" :: "r"(dst), "l"(src))
#define CP_COMMIT() asm volatile("cp.async.commit_group;" ::: "memory")
#define CP_WAIT(n)  asm volatile("cp.async.wait_group %0;" :: "n"(n) : "memory")

#define MMA16816(c, a, b)                                                     \
    asm volatile("mma.sync.aligned.m16n8k16.row.col.f32.f16.f16.f32 "         \
        "{%0,%1,%2,%3},{%4,%5,%6,%7},{%8,%9},{%0,%1,%2,%3};"                  \
        : "+f"((c)[0]), "+f"((c)[1]), "+f"((c)[2]), "+f"((c)[3])              \
        : "r"((a)[0]), "r"((a)[1]), "r"((a)[2]), "r"((a)[3]),                 \
          "r"((b)[0]), "r"((b)[1]))

#define LDSM4(r0, r1, r2, r3, addr)                                           \
    asm volatile("ldmatrix.sync.aligned.m8n8.x4.shared.b16 {%0,%1,%2,%3}, [%4];" \
        : "=r"(r0), "=r"(r1), "=r"(r2), "=r"(r3) : "r"(addr))

__device__ __forceinline__ void split2(float f, h16& h, h16& l) {
    h = __float2half_rn(f);
    l = __float2half_rn(f - __half2float(h));
}

// ------------------------------------------------------------------ precompute
__global__ void k_precomp(const float* __restrict__ Wq, const float* __restrict__ Wk,
                          const float* __restrict__ bq) {
    __shared__ float v[DD];
    int bx = blockIdx.x;
    if (bx < DD) {
        v[threadIdx.x] = Wq[bx*DD + threadIdx.x];
        __syncthreads();
        int j = threadIdx.x;
        const float* wk = Wk + j*DD;
        float s = 0.f;
#pragma unroll 8
        for (int e = 0; e < DD; e++) s += v[e] * wk[e];
        g_W[bx*DD + j] = s;
    } else {
        v[threadIdx.x] = bq[threadIdx.x];
        __syncthreads();
        int i = threadIdx.x;
        const float* wk = Wk + i*DD;
        float s = 0.f;
#pragma unroll 8
        for (int e = 0; e < DD; e++) s += wk[e] * v[e];
        g_u[i] = s;
    }
}

// ------------------------------------------------------------------ fused prep
__global__ __launch_bounds__(256) void k_prep(const float* __restrict__ X,
                                              const float* __restrict__ Wo) {
    __shared__ float t[64][65];
    __shared__ float us[DD];
    int bx = blockIdx.x, tid = threadIdx.x;
    if (bx < 512) {
        int which = bx >> 8, j = bx & 255, d = tid;
        const float* src = which ? Wo : g_W;
        h16* dh = which ? g_Woth : g_Wth;
        h16* dl = which ? g_Wotl : g_Wtl;
        float f = src[d*DD + j];
        split2(f, dh[j*DD + d], dl[j*DD + d]);
    } else if (bx < 4608) {
        if (tid < DD) us[tid] = g_u[tid];
        __syncthreads();
        int warp = (bx - 512)*8 + (tid >> 5);
        int lane = tid & 31;
        const float* x = X + (size_t)warp * DD;
        float c = 0.f;
#pragma unroll
        for (int i = 0; i < 8; i++) {
            int e = lane + 32*i;
            float f = x[e];
            c += f * us[e];
            split2(f, g_Xh[(size_t)warp*DD + e], g_Xl[(size_t)warp*DD + e]);
        }
#pragma unroll
        for (int o = 16; o; o >>= 1) c += __shfl_xor_sync(0xffffffffu, c, o);
        if (lane == 0) g_c[warp] = c;
    } else {
        int idx = bx - 4608;
        int n0 = (idx & 31) * 64, d0 = ((idx >> 5) & 3) * 64, b = idx >> 7;
        const float* Xb = X + (size_t)b * NN * DD;
        for (int u = tid; u < 64*16; u += 256) {
            int r = u >> 4, c4 = u & 15;
            float4 v = *(const float4*)(Xb + (size_t)(n0 + r)*DD + d0 + c4*4);
            t[r][c4*4+0] = v.x; t[r][c4*4+1] = v.y; t[r][c4*4+2] = v.z; t[r][c4*4+3] = v.w;
        }
        __syncthreads();
        size_t ob = (size_t)b * DD * NN;
        for (int u = tid; u < 4096; u += 256) {
            int r = u >> 6, c = u & 63;
            g_Xth[ob + (size_t)(d0 + r)*NN + n0 + c] = __float2half_rn(t[c][r]);
        }
    }
}

// ------------------------------------------------------------------ layout constants
#define TPAD   40
#define TILE_B (128*TPAD*2)       // 10240
#define OFF_AH 0
#define OFF_AL (1*TILE_B)
#define OFF_BH (2*TILE_B)
#define OFF_BL (3*TILE_B)
#define STAGE_B (4*TILE_B)        // 40960
#define GEMM_SMEM (2*STAGE_B)     // 81920
#define SF_SMEM (2*STAGE_B + 3584*4)  // + row-state floats = 96256

// ------------------------------------------------------------------ fused S + softmax strip kernel
// CTA: 128 q-rows x all 2048 keys (16 tiles). Online softmax, Ph + corrections out.
__global__ __launch_bounds__(256, 2) void k_sfuse(
    const h16* __restrict__ Ah, const h16* __restrict__ Al,
    const h16* __restrict__ Bh, const h16* __restrict__ Bl,
    h16* __restrict__ Ph, float* __restrict__ Cfac)
{
    extern __shared__ char smem[];
    uint32_t sb = smem_u32(smem);
    float* fs    = (float*)(smem + 2*STAGE_B);
    float* mrun  = fs;          // [128]
    float* lrun  = fs + 128;    // [128]
    float* bcast = fs + 256;    // [128]
    float* ct    = fs + 384;    // [128]
    float* red   = fs + 512;    // [128][4]
    float* sum   = fs + 1024;   // [128][4]
    float* mtile = fs + 1536;   // [128][16]

    int tid = threadIdx.x;
    int lane = tid & 31, wid = tid >> 5;
    int g = lane >> 2, t = lane & 3;
    int warp_m = (wid & 1) * 64;
    int warp_n = (wid >> 1) * 32;
    int m0 = blockIdx.x * 128, b = blockIdx.z;

    size_t go0 = (size_t)(tid >> 2) * DD + (tid & 3) * 8;
    size_t go1 = go0 + (size_t)64 * DD;
    uint32_t do0 = (uint32_t)((tid >> 2) * 80 + (tid & 3) * 16);
    uint32_t do1 = do0 + 64*80;

    int lr = ((lane >> 3) & 1) * 8 + (lane & 7);
    int lk = (lane >> 4) * 16;
    uint32_t a_off[4], b_off[2];
#pragma unroll
    for (int i = 0; i < 4; i++) a_off[i] = (uint32_t)((warp_m + i*16 + lr)*80 + lk);
#pragma unroll
    for (int p = 0; p < 2; p++) b_off[p] = (uint32_t)((warp_n + p*16 + lr)*80 + lk);

    const h16* pAh = Ah + ((size_t)b*NN + m0)*DD;
    const h16* pAl = Al + ((size_t)b*NN + m0)*DD;
    const h16* pBh0 = Bh + (size_t)b*NN*DD;
    const h16* pBl0 = Bl + (size_t)b*NN*DD;

    if (tid < 128) { mrun[tid] = -1e30f; lrun[tid] = 0.f; }

    auto issue = [&](int gc) {
        uint32_t sbase = sb + (uint32_t)(gc & 1) * STAGE_B;
        int k0 = (gc & 7) << 5;
        const h16* bh = pBh0 + (size_t)(gc >> 3) * 128 * DD;
        const h16* bl = pBl0 + (size_t)(gc >> 3) * 128 * DD;
        CP16(sbase + OFF_AH + do0, pAh + go0 + k0);
        CP16(sbase + OFF_AH + do1, pAh + go1 + k0);
        CP16(sbase + OFF_AL + do0, pAl + go0 + k0);
        CP16(sbase + OFF_AL + do1, pAl + go1 + k0);
        CP16(sbase + OFF_BH + do0, bh + go0 + k0);
        CP16(sbase + OFF_BH + do1, bh + go1 + k0);
        CP16(sbase + OFF_BL + do0, bl + go0 + k0);
        CP16(sbase + OFF_BL + do1, bl + go1 + k0);
    };

    issue(0);
    CP_COMMIT();

    for (int nt = 0; nt < 16; nt++) {
        if (tid < 128) ct[tid] = g_c[b*NN + nt*128 + tid];

        float acc[4][4][4];
#pragma unroll
        for (int i = 0; i < 4; i++)
#pragma unroll
            for (int j = 0; j < 4; j++)
#pragma unroll
                for (int r = 0; r < 4; r++) acc[i][j][r] = 0.f;

        for (int ch = 0; ch < 8; ch++) {
            int gc = nt*8 + ch;
            if (gc + 1 < 128) {
                issue(gc + 1);
                CP_COMMIT();
                CP_WAIT(1);
            } else {
                CP_WAIT(0);
            }
            __syncthreads();

            uint32_t base = sb + (uint32_t)(gc & 1) * STAGE_B;
#pragma unroll
            for (int ks = 0; ks < 2; ks++) {
                uint32_t kb = ks * 32;
                uint32_t ah[4][4], al[4][4], bh[4][2], bl[4][2];
#pragma unroll
                for (int i = 0; i < 4; i++) {
                    LDSM4(ah[i][0], ah[i][1], ah[i][2], ah[i][3], base + OFF_AH + a_off[i] + kb);
                    LDSM4(al[i][0], al[i][1], al[i][2], al[i][3], base + OFF_AL + a_off[i] + kb);
                }
#pragma unroll
                for (int p = 0; p < 2; p++) {
                    LDSM4(bh[2*p][0], bh[2*p+1][0], bh[2*p][1], bh[2*p+1][1],
                          base + OFF_BH + b_off[p] + kb);
                    LDSM4(bl[2*p][0], bl[2*p+1][0], bl[2*p][1], bl[2*p+1][1],
                          base + OFF_BL + b_off[p] + kb);
                }
#pragma unroll
                for (int i = 0; i < 4; i++)
#pragma unroll
                    for (int j = 0; j < 4; j++) {
                        MMA16816(acc[i][j], ah[i], bh[j]);
                        MMA16816(acc[i][j], ah[i], bl[j]);
                        MMA16816(acc[i][j], al[i], bh[j]);
                    }
            }
            __syncthreads();
        }

        // ---- epilogue: c-add, tile row-max, online update, exp, Ph, sums ----
        float mA[4], mB[4];
#pragma unroll
        for (int i = 0; i < 4; i++) {
            mA[i] = -1e30f; mB[i] = -1e30f;
#pragma unroll
            for (int j = 0; j < 4; j++) {
                int cl = warp_n + j*8 + 2*t;
                float c0 = ct[cl], c1 = ct[cl+1];
                acc[i][j][0] += c0; acc[i][j][1] += c1;
                acc[i][j][2] += c0; acc[i][j][3] += c1;
                mA[i] = fmaxf(mA[i], fmaxf(acc[i][j][0], acc[i][j][1]));
                mB[i] = fmaxf(mB[i], fmaxf(acc[i][j][2], acc[i][j][3]));
            }
            mA[i] = fmaxf(mA[i], __shfl_xor_sync(0xffffffffu, mA[i], 1));
            mA[i] = fmaxf(mA[i], __shfl_xor_sync(0xffffffffu, mA[i], 2));
            mB[i] = fmaxf(mB[i], __shfl_xor_sync(0xffffffffu, mB[i], 1));
            mB[i] = fmaxf(mB[i], __shfl_xor_sync(0xffffffffu, mB[i], 2));
        }
        if (t == 0) {
#pragma unroll
            for (int i = 0; i < 4; i++) {
                red[(warp_m + i*16 + g)*4 + (wid >> 1)]     = mA[i];
                red[(warp_m + i*16 + g + 8)*4 + (wid >> 1)] = mB[i];
            }
        }
        __syncthreads();
        if (tid < 128) {
            float mt = fmaxf(fmaxf(red[tid*4], red[tid*4+1]),
                             fmaxf(red[tid*4+2], red[tid*4+3]));
            float mo = mrun[tid];
            float mn = fmaxf(mo, mt);
            lrun[tid] *= __expf(mo - mn);
            mrun[tid] = mn;
            mtile[tid*16 + nt] = mn;
            bcast[tid] = mn;
        }
        __syncthreads();
#pragma unroll
        for (int i = 0; i < 4; i++) {
            int rA = warp_m + i*16 + g, rB = rA + 8;
            float emA = bcast[rA], emB = bcast[rB];
            float sA = 0.f, sB = 0.f;
            size_t oA = ((size_t)b*NN + m0 + rA)*NN + nt*128;
            size_t oB = oA + 8*(size_t)NN;
#pragma unroll
            for (int j = 0; j < 4; j++) {
                int cl = warp_n + j*8 + 2*t;
                float p0 = __expf(acc[i][j][0] - emA), p1 = __expf(acc[i][j][1] - emA);
                float p2 = __expf(acc[i][j][2] - emB), p3 = __expf(acc[i][j][3] - emB);
                sA += p0 + p1; sB += p2 + p3;
                *(__half2*)(Ph + oA + cl) = __floats2half2_rn(p0, p1);
                *(__half2*)(Ph + oB + cl) = __floats2half2_rn(p2, p3);
            }
            sA += __shfl_xor_sync(0xffffffffu, sA, 1);
            sA += __shfl_xor_sync(0xffffffffu, sA, 2);
            sB += __shfl_xor_sync(0xffffffffu, sB, 1);
            sB += __shfl_xor_sync(0xffffffffu, sB, 2);
            if (t == 0) {
                sum[rA*4 + (wid >> 1)] = sA;
                sum[rB*4 + (wid >> 1)] = sB;
            }
        }
        __syncthreads();
        if (tid < 128)
            lrun[tid] += sum[tid*4] + sum[tid*4+1] + sum[tid*4+2] + sum[tid*4+3];
        __syncthreads();
    }

    // ---- corrections: Cfac[row][t] = exp(m_t - m_final) / l_final ----
    if (tid < 128) {
        float mf = mrun[tid];
        float li = 1.f / lrun[tid];
        size_t base = ((size_t)b*NN + m0 + tid) * 16;
#pragma unroll
        for (int q = 0; q < 16; q++)
            Cfac[base + q] = __expf(mtile[tid*16 + q] - mf) * li;
    }
}

// ------------------------------------------------------------------ HMMA GEMM
// COMBOS: 3 = Ah.Bh + Ah.Bl + Al.Bh   1 = Ah.Bh
// SCA: scale A fragments by per-(row, ktile) Cfac (PV normalization).
// EPI: 1 = fp16 hi/lo split   2 = bias+relu fp32
template<int EPI, int COMBOS, bool SCA>
__global__ __launch_bounds__(256, 2) void k_gemm(
    const h16* __restrict__ Ah, const h16* __restrict__ Al,
    const h16* __restrict__ Bh, const h16* __restrict__ Bl,
    float* __restrict__ Cf, h16* __restrict__ Ch, h16* __restrict__ Cl,
    const float* __restrict__ bias, const float* __restrict__ Cfac,
    int K, int ldc, size_t sA, size_t sB, size_t sC)
{
    extern __shared__ char smem[];
    uint32_t sb = smem_u32(smem);
    int tid = threadIdx.x;
    int lane = tid & 31, wid = tid >> 5;
    int g = lane >> 2, t = lane & 3;
    int warp_m = (wid & 1) * 64;
    int warp_n = (wid >> 1) * 32;
    int m0 = blockIdx.x * 128, n0 = blockIdx.y * 128, b = blockIdx.z;

    size_t go0 = (size_t)(tid >> 2) * K + (tid & 3) * 8;
    size_t go1 = go0 + (size_t)64 * K;
    uint32_t do0 = (uint32_t)((tid >> 2) * 80 + (tid & 3) * 16);
    uint32_t do1 = do0 + 64*80;

    int lr = ((lane >> 3) & 1) * 8 + (lane & 7);
    int lk = (lane >> 4) * 16;
    uint32_t a_off[4], b_off[2];
#pragma unroll
    for (int i = 0; i < 4; i++) a_off[i] = (uint32_t)((warp_m + i*16 + lr)*80 + lk);
#pragma unroll
    for (int p = 0; p < 2; p++) b_off[p] = (uint32_t)((warp_n + p*16 + lr)*80 + lk);

    const h16* pAh = Ah + (size_t)b*sA + (size_t)m0*K;
    const h16* pAl = (COMBOS >= 3) ? Al + (size_t)b*sA + (size_t)m0*K : nullptr;
    const h16* pBh = Bh + (size_t)b*sB + (size_t)n0*K;
    const h16* pBl = (COMBOS >= 2) ? Bl + (size_t)b*sB + (size_t)n0*K : nullptr;

    float acc[4][4][4];
#pragma unroll
    for (int i = 0; i < 4; i++)
#pragma unroll
        for (int j = 0; j < 4; j++)
#pragma unroll
            for (int r = 0; r < 4; r++) acc[i][j][r] = 0.f;

#define ISSUE_CHUNK(sbase, k0) do {                                          \
        CP16((sbase) + OFF_AH + do0, pAh + go0 + (k0));                      \
        CP16((sbase) + OFF_AH + do1, pAh + go1 + (k0));                      \
        if (COMBOS >= 3) {                                                   \
            CP16((sbase) + OFF_AL + do0, pAl + go0 + (k0));                  \
            CP16((sbase) + OFF_AL + do1, pAl + go1 + (k0));                  \
        }                                                                    \
        CP16((sbase) + OFF_BH + do0, pBh + go0 + (k0));                      \
        CP16((sbase) + OFF_BH + do1, pBh + go1 + (k0));                      \
        if (COMBOS >= 2) {                                                   \
            CP16((sbase) + OFF_BL + do0, pBl + go0 + (k0));                  \
            CP16((sbase) + OFF_BL + do1, pBl + go1 + (k0));                  \
        }                                                                    \
    } while (0)

    int nchunk = K >> 5;
    ISSUE_CHUNK(sb, 0);
    CP_COMMIT();

    __half2 hA[4], hB[4];

    for (int ch = 0; ch < nchunk; ch++) {
        int st = ch & 1;
        if (ch + 1 < nchunk) {
            ISSUE_CHUNK(sb + (uint32_t)(st ^ 1)*STAGE_B, (ch+1) << 5);
            CP_COMMIT();
            CP_WAIT(1);
        } else {
            CP_WAIT(0);
        }

        if (SCA && (ch & 3) == 0) {
            int kt = ch >> 2;
#pragma unroll
            for (int i = 0; i < 4; i++) {
                float fA = Cfac[((size_t)b*NN + m0 + warp_m + i*16 + g)*16 + kt];
                float fB = Cfac[((size_t)b*NN + m0 + warp_m + i*16 + g + 8)*16 + kt];
                hA[i] = __half2half2(__float2half_rn(fA));
                hB[i] = __half2half2(__float2half_rn(fB));
            }
        }
        __syncthreads();

        uint32_t base = sb + (uint32_t)st * STAGE_B;
#pragma unroll
        for (int ks = 0; ks < 2; ks++) {
            uint32_t kb = ks * 32;
            uint32_t ah[4][4], al[4][4], bh[4][2], bl[4][2];
#pragma unroll
            for (int i = 0; i < 4; i++) {
                LDSM4(ah[i][0], ah[i][1], ah[i][2], ah[i][3], base + OFF_AH + a_off[i] + kb);
                if (SCA) {
                    *(__half2*)&ah[i][0] = __hmul2(*(__half2*)&ah[i][0], hA[i]);
                    *(__half2*)&ah[i][1] = __hmul2(*(__half2*)&ah[i][1], hB[i]);
                    *(__half2*)&ah[i][2] = __hmul2(*(__half2*)&ah[i][2], hA[i]);
                    *(__half2*)&ah[i][3] = __hmul2(*(__half2*)&ah[i][3], hB[i]);
                }
                if (COMBOS >= 3)
                    LDSM4(al[i][0], al[i][1], al[i][2], al[i][3], base + OFF_AL + a_off[i] + kb);
            }
#pragma unroll
            for (int p = 0; p < 2; p++) {
                LDSM4(bh[2*p][0], bh[2*p+1][0], bh[2*p][1], bh[2*p+1][1],
                      base + OFF_BH + b_off[p] + kb);
                if (COMBOS >= 2)
                    LDSM4(bl[2*p][0], bl[2*p+1][0], bl[2*p][1], bl[2*p+1][1],
                          base + OFF_BL + b_off[p] + kb);
            }
#pragma unroll
            for (int i = 0; i < 4; i++)
#pragma unroll
                for (int j = 0; j < 4; j++) {
                    MMA16816(acc[i][j], ah[i], bh[j]);
                    if (COMBOS >= 2) MMA16816(acc[i][j], ah[i], bl[j]);
                    if (COMBOS >= 3) MMA16816(acc[i][j], al[i], bh[j]);
                }
        }
        __syncthreads();
    }

    // ---- epilogue ----
#pragma unroll
    for (int i = 0; i < 4; i++) {
        int row0 = m0 + warp_m + i*16 + g;
#pragma unroll
        for (int j = 0; j < 4; j++) {
            int col = n0 + warp_n + j*8 + 2*t;
            if (EPI == 1) {
                float v0 = acc[i][j][0], v1 = acc[i][j][1];
                float v2 = acc[i][j][2], v3 = acc[i][j][3];
                h16 h0, l0, h1, l1, h2, l2, h3, l3;
                split2(v0, h0, l0); split2(v1, h1, l1);
                split2(v2, h2, l2); split2(v3, h3, l3);
                size_t o0 = (size_t)b*sC + (size_t)row0*ldc + col;
                size_t o1 = o0 + 8*(size_t)ldc;
                *(__half2*)(Ch + o0) = __halves2half2(h0, h1);
                *(__half2*)(Ch + o1) = __halves2half2(h2, h3);
                *(__half2*)(Cl + o0) = __halves2half2(l0, l1);
                *(__half2*)(Cl + o1) = __halves2half2(l2, l3);
            } else {
                float b0 = bias[col], b1 = bias[col+1];
                float* d0 = Cf + (size_t)row0*ldc + col;
                float* d1 = d0 + 8*ldc;
                *(float2*)d0 = make_float2(fmaxf(acc[i][j][0]+b0, 0.f),
                                           fmaxf(acc[i][j][1]+b1, 0.f));
                *(float2*)d1 = make_float2(fmaxf(acc[i][j][2]+b0, 0.f),
                                           fmaxf(acc[i][j][3]+b1, 0.f));
            }
        }
    }
#undef ISSUE_CHUNK
}

// ------------------------------------------------------------------ launch
extern "C" void kernel_launch(void* const* d_in, const int* in_sizes, int n_in,
                              void* d_out, int out_size) {
    const float* inp = (const float*)d_in[0];
    const float* Wq  = (const float*)d_in[1];
    const float* bq  = (const float*)d_in[2];
    const float* Wk  = (const float*)d_in[3];
    // bk (d_in[4]) provably drops out of the softmax — unused.
    const float* Wo  = (const float*)d_in[5];
    const float* bo  = (const float*)d_in[6];
    float* out = (float*)d_out;

    float *pC;
    h16 *pXh, *pXl, *pXth, *pAph, *pApl, *pPh, *pAggh, *pAggl;
    h16 *pWth, *pWtl, *pWoth, *pWotl;
    cudaGetSymbolAddress((void**)&pC, g_C);
    cudaGetSymbolAddress((void**)&pXh, g_Xh);   cudaGetSymbolAddress((void**)&pXl, g_Xl);
    cudaGetSymbolAddress((void**)&pXth, g_Xth);
    cudaGetSymbolAddress((void**)&pAph, g_Aph); cudaGetSymbolAddress((void**)&pApl, g_Apl);
    cudaGetSymbolAddress((void**)&pPh, g_Ph);
    cudaGetSymbolAddress((void**)&pAggh, g_aggh); cudaGetSymbolAddress((void**)&pAggl, g_aggl);
    cudaGetSymbolAddress((void**)&pWth, g_Wth); cudaGetSymbolAddress((void**)&pWtl, g_Wtl);
    cudaGetSymbolAddress((void**)&pWoth, g_Woth); cudaGetSymbolAddress((void**)&pWotl, g_Wotl);

    cudaFuncSetAttribute((const void*)k_gemm<1,3,false>, cudaFuncAttributeMaxDynamicSharedMemorySize, GEMM_SMEM);
    cudaFuncSetAttribute((const void*)k_gemm<1,1,true>,  cudaFuncAttributeMaxDynamicSharedMemorySize, GEMM_SMEM);
    cudaFuncSetAttribute((const void*)k_gemm<2,3,false>, cudaFuncAttributeMaxDynamicSharedMemorySize, GEMM_SMEM);
    cudaFuncSetAttribute((const void*)k_sfuse, cudaFuncAttributeMaxDynamicSharedMemorySize, SF_SMEM);

    // 1) W = Wq Wk^T, u = Wk bq
    k_precomp<<<DD + 1, DD>>>(Wq, Wk, bq);
    // 2) all splits/transposes + c
    k_prep<<<6656, 256>>>(inp, Wo);
    // 3) A' = X @ W -> fp16 splits  (3 combos)
    k_gemm<1,3,false><<<dim3(ROWS/128, 2, 1), 256, GEMM_SMEM>>>(
        pXh, pXl, pWth, pWtl, nullptr, pAph, pApl, nullptr, nullptr,
        DD, DD, 0, 0, 0);
    // 4) fused S + softmax strips -> Ph + Cfac   [profiled slot]
    k_sfuse<<<dim3(NN/128, 1, BB), 256, SF_SMEM>>>(
        pAph, pApl, pXh, pXl, pPh, pC);
    // 5) agg = sum_kt Cfac*Ph @ Xth  (K=2048, 1 combo, A scaled) -> fp16 splits
    k_gemm<1,1,true><<<dim3(NN/128, 2, BB), 256, GEMM_SMEM>>>(
        pPh, nullptr, pXth, nullptr, nullptr, pAggh, pAggl, nullptr, pC,
        NN, DD, (size_t)NN*NN, (size_t)DD*NN, (size_t)NN*DD);
    // 6) out = relu(agg @ Wo + bo) -> fp32  (3 combos)
    k_gemm<2,3,false><<<dim3(ROWS/128, 2, 1), 256, GEMM_SMEM>>>(
        pAggh, pAggl, pWoth, pWotl, out, nullptr, nullptr, bo, nullptr,
        DD, DD, 0, 0, 0);
}

// round 9
// speedup vs baseline: 1.0935x; 1.0935x over previous
#include <cuda_runtime.h>
#include <cuda_fp16.h>
#include <cstdint>

#define DD 256
#define BB 16
#define NN 2048
#define ROWS (BB*NN)

typedef __half h16;

// ------------------------------------------------------------------ scratch
__device__ float g_W[DD*DD];                 // Wq @ Wk^T
__device__ float g_u[DD];                    // Wk @ bq
__device__ float g_c[ROWS];                  // X . u  (per key row)
__device__ float g_invl[ROWS];               // 1 / sum(Ph)
__device__ float g_S[(size_t)ROWS*NN];       // scores + c (268MB)

__device__ h16 g_Xh[(size_t)ROWS*DD],  g_Xl[(size_t)ROWS*DD];    // X splits (row-major)
__device__ h16 g_Xth[(size_t)BB*DD*NN];                          // X^T (hi only)
__device__ h16 g_Aph[(size_t)ROWS*DD], g_Apl[(size_t)ROWS*DD];   // A' = X@W splits
__device__ h16 g_Ph[(size_t)ROWS*NN];                            // softmax (hi only)
__device__ h16 g_aggh[(size_t)ROWS*DD], g_aggl[(size_t)ROWS*DD]; // agg splits
__device__ h16 g_Wth[DD*DD], g_Wtl[DD*DD];   // (WqWk^T)^T splits
__device__ h16 g_Woth[DD*DD], g_Wotl[DD*DD]; // Wo^T splits

// ------------------------------------------------------------------ helpers
__device__ __forceinline__ uint32_t smem_u32(const void* p) {
    uint32_t a;
    asm("{ .reg .u64 t; cvta.to.shared.u64 t, %1; cvt.u32.u64 %0, t; }" : "=r"(a) : "l"(p));
    return a;
}
#define CP16(dst, src) \
    asm volatile("cp.async.cg.shared.global [%0], [%1], 16;" :: "r"(dst), "l"(src))
#define CP_COMMIT() asm volatile("cp.async.commit_group;" ::: "memory")
#define CP_WAIT(n)  asm volatile("cp.async.wait_group %0;" :: "n"(n) : "memory")

#define MMA16816(c, a, b)                                                     \
    asm volatile("mma.sync.aligned.m16n8k16.row.col.f32.f16.f16.f32 "         \
        "{%0,%1,%2,%3},{%4,%5,%6,%7},{%8,%9},{%0,%1,%2,%3};"                  \
        : "+f"((c)[0]), "+f"((c)[1]), "+f"((c)[2]), "+f"((c)[3])              \
        : "r"((a)[0]), "r"((a)[1]), "r"((a)[2]), "r"((a)[3]),                 \
          "r"((b)[0]), "r"((b)[1]))

#define LDSM4(r0, r1, r2, r3, addr)                                           \
    asm volatile("ldmatrix.sync.aligned.m8n8.x4.shared.b16 {%0,%1,%2,%3}, [%4];" \
        : "=r"(r0), "=r"(r1), "=r"(r2), "=r"(r3) : "r"(addr))

__device__ __forceinline__ void split2(float f, h16& h, h16& l) {
    h = __float2half_rn(f);
    l = __float2half_rn(f - __half2float(h));
}

// ------------------------------------------------------------------ precompute: W = Wq@Wk^T, u = Wk@bq
__global__ void k_precomp(const float* __restrict__ Wq, const float* __restrict__ Wk,
                          const float* __restrict__ bq) {
    __shared__ float v[DD];
    int bx = blockIdx.x;
    if (bx < DD) {
        v[threadIdx.x] = Wq[bx*DD + threadIdx.x];
        __syncthreads();
        int j = threadIdx.x;
        const float* wk = Wk + j*DD;
        float s = 0.f;
#pragma unroll 8
        for (int e = 0; e < DD; e++) s += v[e] * wk[e];
        g_W[bx*DD + j] = s;
    } else {
        v[threadIdx.x] = bq[threadIdx.x];
        __syncthreads();
        int i = threadIdx.x;
        const float* wk = Wk + i*DD;
        float s = 0.f;
#pragma unroll 8
        for (int e = 0; e < DD; e++) s += wk[e] * v[e];
        g_u[i] = s;
    }
}

// ------------------------------------------------------------------ fused prep
__global__ __launch_bounds__(256) void k_prep(const float* __restrict__ X,
                                              const float* __restrict__ Wo) {
    __shared__ float t[64][65];
    __shared__ float us[DD];
    int bx = blockIdx.x, tid = threadIdx.x;
    if (bx < 512) {
        int which = bx >> 8, j = bx & 255, d = tid;
        const float* src = which ? Wo : g_W;
        h16* dh = which ? g_Woth : g_Wth;
        h16* dl = which ? g_Wotl : g_Wtl;
        float f = src[d*DD + j];
        split2(f, dh[j*DD + d], dl[j*DD + d]);
    } else if (bx < 4608) {
        if (tid < DD) us[tid] = g_u[tid];
        __syncthreads();
        int warp = (bx - 512)*8 + (tid >> 5);
        int lane = tid & 31;
        const float* x = X + (size_t)warp * DD;
        float c = 0.f;
#pragma unroll
        for (int i = 0; i < 8; i++) {
            int e = lane + 32*i;
            float f = x[e];
            c += f * us[e];
            split2(f, g_Xh[(size_t)warp*DD + e], g_Xl[(size_t)warp*DD + e]);
        }
#pragma unroll
        for (int o = 16; o; o >>= 1) c += __shfl_xor_sync(0xffffffffu, c, o);
        if (lane == 0) g_c[warp] = c;
    } else {
        int idx = bx - 4608;
        int n0 = (idx & 31) * 64, d0 = ((idx >> 5) & 3) * 64, b = idx >> 7;
        const float* Xb = X + (size_t)b * NN * DD;
        for (int u = tid; u < 64*16; u += 256) {
            int r = u >> 4, c4 = u & 15;
            float4 v = *(const float4*)(Xb + (size_t)(n0 + r)*DD + d0 + c4*4);
            t[r][c4*4+0] = v.x; t[r][c4*4+1] = v.y; t[r][c4*4+2] = v.z; t[r][c4*4+3] = v.w;
        }
        __syncthreads();
        size_t ob = (size_t)b * DD * NN;
        for (int u = tid; u < 4096; u += 256) {
            int r = u >> 6, c = u & 63;
            g_Xth[ob + (size_t)(d0 + r)*NN + n0 + c] = __float2half_rn(t[c][r]);
        }
    }
}

// warp per row softmax (vectorized; c already folded into S)
__global__ __launch_bounds__(256) void k_softmax() {
    int warp = (blockIdx.x * blockDim.x + threadIdx.x) >> 5;
    int lane = threadIdx.x & 31;
    const float* srow = g_S + (size_t)warp * NN;
    float4 v4[16];
    float mx = -1e30f;
#pragma unroll
    for (int i = 0; i < 16; i++) {
        float4 s = *(const float4*)(srow + i*128 + lane*4);
        v4[i] = s;
        mx = fmaxf(mx, fmaxf(fmaxf(s.x, s.y), fmaxf(s.z, s.w)));
    }
#pragma unroll
    for (int o = 16; o; o >>= 1) mx = fmaxf(mx, __shfl_xor_sync(0xffffffffu, mx, o));
    float sum = 0.f;
    size_t ro = (size_t)warp * NN;
#pragma unroll
    for (int i = 0; i < 16; i++) {
        float e0 = __expf(v4[i].x - mx), e1 = __expf(v4[i].y - mx);
        float e2 = __expf(v4[i].z - mx), e3 = __expf(v4[i].w - mx);
        h16 h0 = __float2half_rn(e0), h1 = __float2half_rn(e1);
        h16 h2 = __float2half_rn(e2), h3 = __float2half_rn(e3);
        sum += __half2float(h0) + __half2float(h1) + __half2float(h2) + __half2float(h3);
        __half2 p01 = __halves2half2(h0, h1), p23 = __halves2half2(h2, h3);
        uint2 pk;
        pk.x = *reinterpret_cast<uint32_t*>(&p01);
        pk.y = *reinterpret_cast<uint32_t*>(&p23);
        *(uint2*)(g_Ph + ro + i*128 + lane*4) = pk;
    }
#pragma unroll
    for (int o = 16; o; o >>= 1) sum += __shfl_xor_sync(0xffffffffu, sum, o);
    if (lane == 0) g_invl[warp] = 1.f / sum;
}

// ------------------------------------------------------------------ HMMA GEMM
// COMBOS: 3 = Ah.Bh + Ah.Bl + Al.Bh   1 = Ah.Bh
#define TPAD   40
#define TILE_B (128*TPAD*2)       // 10240
#define OFF_AH 0
#define OFF_AL (1*TILE_B)
#define OFF_BH (2*TILE_B)
#define OFF_BL (3*TILE_B)
#define STAGE_B (4*TILE_B)        // 40960
#define GEMM_SMEM (2*STAGE_B)     // 81920 -> two CTAs per SM

// EPI: 0 = fp32 + per-column bias (batch-indexed: c fold)   1 = fp16 split + 1/l scale
//      2 = bias+relu fp32
template<int EPI, int COMBOS>
__global__ __launch_bounds__(256, 2) void k_gemm(
    const h16* __restrict__ Ah, const h16* __restrict__ Al,
    const h16* __restrict__ Bh, const h16* __restrict__ Bl,
    float* __restrict__ Cf, h16* __restrict__ Ch, h16* __restrict__ Cl,
    const float* __restrict__ bias, const float* __restrict__ invl,
    int K, int ldc, int Mrows, size_t sA, size_t sB, size_t sC)
{
    extern __shared__ char smem[];
    uint32_t sb = smem_u32(smem);
    int tid = threadIdx.x;
    int lane = tid & 31, wid = tid >> 5;
    int g = lane >> 2, t = lane & 3;
    int warp_m = (wid & 1) * 64;
    int warp_n = (wid >> 1) * 32;
    int m0 = blockIdx.x * 128, n0 = blockIdx.y * 128, b = blockIdx.z;

    size_t go0 = (size_t)(tid >> 2) * K + (tid & 3) * 8;
    size_t go1 = go0 + (size_t)64 * K;
    uint32_t do0 = (uint32_t)((tid >> 2) * 80 + (tid & 3) * 16);
    uint32_t do1 = do0 + 64*80;

    int lr = ((lane >> 3) & 1) * 8 + (lane & 7);
    int lk = (lane >> 4) * 16;
    uint32_t a_off[4], b_off[2];
#pragma unroll
    for (int i = 0; i < 4; i++) a_off[i] = (uint32_t)((warp_m + i*16 + lr)*80 + lk);
#pragma unroll
    for (int p = 0; p < 2; p++) b_off[p] = (uint32_t)((warp_n + p*16 + lr)*80 + lk);

    const h16* pAh = Ah + (size_t)b*sA + (size_t)m0*K;
    const h16* pAl = (COMBOS >= 3) ? Al + (size_t)b*sA + (size_t)m0*K : nullptr;
    const h16* pBh = Bh + (size_t)b*sB + (size_t)n0*K;
    const h16* pBl = (COMBOS >= 2) ? Bl + (size_t)b*sB + (size_t)n0*K : nullptr;

    // hoisted epilogue scales (PV: 1/l per row) — load before mainloop
    float sc0[4], sc1[4];
    if (EPI == 1 && invl) {
#pragma unroll
        for (int i = 0; i < 4; i++) {
            sc0[i] = invl[(size_t)b*Mrows + m0 + warp_m + i*16 + g];
            sc1[i] = invl[(size_t)b*Mrows + m0 + warp_m + i*16 + g + 8];
        }
    } else {
#pragma unroll
        for (int i = 0; i < 4; i++) { sc0[i] = 1.f; sc1[i] = 1.f; }
    }

    float acc[4][4][4];
#pragma unroll
    for (int i = 0; i < 4; i++)
#pragma unroll
        for (int j = 0; j < 4; j++)
#pragma unroll
            for (int r = 0; r < 4; r++) acc[i][j][r] = 0.f;

#define ISSUE_CHUNK(sbase, k0) do {                                          \
        CP16((sbase) + OFF_AH + do0, pAh + go0 + (k0));                      \
        CP16((sbase) + OFF_AH + do1, pAh + go1 + (k0));                      \
        if (COMBOS >= 3) {                                                   \
            CP16((sbase) + OFF_AL + do0, pAl + go0 + (k0));                  \
            CP16((sbase) + OFF_AL + do1, pAl + go1 + (k0));                  \
        }                                                                    \
        CP16((sbase) + OFF_BH + do0, pBh + go0 + (k0));                      \
        CP16((sbase) + OFF_BH + do1, pBh + go1 + (k0));                      \
        if (COMBOS >= 2) {                                                   \
            CP16((sbase) + OFF_BL + do0, pBl + go0 + (k0));                  \
            CP16((sbase) + OFF_BL + do1, pBl + go1 + (k0));                  \
        }                                                                    \
    } while (0)

    int nchunk = K >> 5;
    ISSUE_CHUNK(sb, 0);
    CP_COMMIT();

    for (int ch = 0; ch < nchunk; ch++) {
        int st = ch & 1;
        if (ch + 1 < nchunk) {
            ISSUE_CHUNK(sb + (uint32_t)(st ^ 1)*STAGE_B, (ch+1) << 5);
            CP_COMMIT();
            CP_WAIT(1);
        } else {
            CP_WAIT(0);
        }
        __syncthreads();

        uint32_t base = sb + (uint32_t)st * STAGE_B;
#pragma unroll
        for (int ks = 0; ks < 2; ks++) {
            uint32_t kb = ks * 32;
            uint32_t ah[4][4], al[4][4], bh[4][2], bl[4][2];
#pragma unroll
            for (int i = 0; i < 4; i++) {
                LDSM4(ah[i][0], ah[i][1], ah[i][2], ah[i][3], base + OFF_AH + a_off[i] + kb);
                if (COMBOS >= 3)
                    LDSM4(al[i][0], al[i][1], al[i][2], al[i][3], base + OFF_AL + a_off[i] + kb);
            }
#pragma unroll
            for (int p = 0; p < 2; p++) {
                LDSM4(bh[2*p][0], bh[2*p+1][0], bh[2*p][1], bh[2*p+1][1],
                      base + OFF_BH + b_off[p] + kb);
                if (COMBOS >= 2)
                    LDSM4(bl[2*p][0], bl[2*p+1][0], bl[2*p][1], bl[2*p+1][1],
                          base + OFF_BL + b_off[p] + kb);
            }
#pragma unroll
            for (int i = 0; i < 4; i++)
#pragma unroll
                for (int j = 0; j < 4; j++) {
                    MMA16816(acc[i][j], ah[i], bh[j]);
                    if (COMBOS >= 2) MMA16816(acc[i][j], ah[i], bl[j]);
                    if (COMBOS >= 3) MMA16816(acc[i][j], al[i], bh[j]);
                }
        }
        __syncthreads();
    }

    // ---- epilogue ----
#pragma unroll
    for (int i = 0; i < 4; i++) {
        int row0 = m0 + warp_m + i*16 + g;
#pragma unroll
        for (int j = 0; j < 4; j++) {
            int col = n0 + warp_n + j*8 + 2*t;
            if (EPI == 0) {
                // S output: add per-column c (bias indexed per batch)
                float c0 = bias[(size_t)b*ldc + col], c1 = bias[(size_t)b*ldc + col + 1];
                float* d0 = Cf + (size_t)b*sC + (size_t)row0*ldc + col;
                float* d1 = d0 + 8*ldc;
                *(float2*)d0 = make_float2(acc[i][j][0] + c0, acc[i][j][1] + c1);
                *(float2*)d1 = make_float2(acc[i][j][2] + c0, acc[i][j][3] + c1);
            } else if (EPI == 1) {
                float v0 = acc[i][j][0]*sc0[i], v1 = acc[i][j][1]*sc0[i];
                float v2 = acc[i][j][2]*sc1[i], v3 = acc[i][j][3]*sc1[i];
                h16 h0, l0, h1, l1, h2, l2, h3, l3;
                split2(v0, h0, l0); split2(v1, h1, l1);
                split2(v2, h2, l2); split2(v3, h3, l3);
                size_t o0 = (size_t)b*sC + (size_t)row0*ldc + col;
                size_t o1 = o0 + 8*(size_t)ldc;
                *(__half2*)(Ch + o0) = __halves2half2(h0, h1);
                *(__half2*)(Ch + o1) = __halves2half2(h2, h3);
                *(__half2*)(Cl + o0) = __halves2half2(l0, l1);
                *(__half2*)(Cl + o1) = __halves2half2(l2, l3);
            } else {
                float b0 = bias[col], b1 = bias[col+1];
                float* d0 = Cf + (size_t)row0*ldc + col;
                float* d1 = d0 + 8*ldc;
                *(float2*)d0 = make_float2(fmaxf(acc[i][j][0]+b0, 0.f),
                                           fmaxf(acc[i][j][1]+b1, 0.f));
                *(float2*)d1 = make_float2(fmaxf(acc[i][j][2]+b0, 0.f),
                                           fmaxf(acc[i][j][3]+b1, 0.f));
            }
        }
    }
#undef ISSUE_CHUNK
}

// ------------------------------------------------------------------ launch
extern "C" void kernel_launch(void* const* d_in, const int* in_sizes, int n_in,
                              void* d_out, int out_size) {
    const float* inp = (const float*)d_in[0];
    const float* Wq  = (const float*)d_in[1];
    const float* bq  = (const float*)d_in[2];
    const float* Wk  = (const float*)d_in[3];
    // bk (d_in[4]) provably drops out of the softmax — unused.
    const float* Wo  = (const float*)d_in[5];
    const float* bo  = (const float*)d_in[6];
    float* out = (float*)d_out;

    float *pS, *pInvl, *pCvec;
    h16 *pXh, *pXl, *pXth, *pAph, *pApl, *pPh, *pAggh, *pAggl;
    h16 *pWth, *pWtl, *pWoth, *pWotl;
    cudaGetSymbolAddress((void**)&pS, g_S);
    cudaGetSymbolAddress((void**)&pInvl, g_invl);
    cudaGetSymbolAddress((void**)&pCvec, g_c);
    cudaGetSymbolAddress((void**)&pXh, g_Xh);   cudaGetSymbolAddress((void**)&pXl, g_Xl);
    cudaGetSymbolAddress((void**)&pXth, g_Xth);
    cudaGetSymbolAddress((void**)&pAph, g_Aph); cudaGetSymbolAddress((void**)&pApl, g_Apl);
    cudaGetSymbolAddress((void**)&pPh, g_Ph);
    cudaGetSymbolAddress((void**)&pAggh, g_aggh); cudaGetSymbolAddress((void**)&pAggl, g_aggl);
    cudaGetSymbolAddress((void**)&pWth, g_Wth); cudaGetSymbolAddress((void**)&pWtl, g_Wtl);
    cudaGetSymbolAddress((void**)&pWoth, g_Woth); cudaGetSymbolAddress((void**)&pWotl, g_Wotl);

    cudaFuncSetAttribute((const void*)k_gemm<0,3>, cudaFuncAttributeMaxDynamicSharedMemorySize, GEMM_SMEM);
    cudaFuncSetAttribute((const void*)k_gemm<1,3>, cudaFuncAttributeMaxDynamicSharedMemorySize, GEMM_SMEM);
    cudaFuncSetAttribute((const void*)k_gemm<1,1>, cudaFuncAttributeMaxDynamicSharedMemorySize, GEMM_SMEM);
    cudaFuncSetAttribute((const void*)k_gemm<2,3>, cudaFuncAttributeMaxDynamicSharedMemorySize, GEMM_SMEM);

    // 1) W = Wq Wk^T, u = Wk bq
    k_precomp<<<DD + 1, DD>>>(Wq, Wk, bq);
    // 2) all splits/transposes + c
    k_prep<<<6656, 256>>>(inp, Wo);
    // 3) A' = X @ W -> fp16 splits  (3 combos)
    k_gemm<1,3><<<dim3(ROWS/128, 2, 1), 256, GEMM_SMEM>>>(
        pXh, pXl, pWth, pWtl, nullptr, pAph, pApl, nullptr, nullptr,
        DD, DD, ROWS, 0, 0, 0);
    // 4) S = A' @ X^T + c  (per batch 2048x2048, K=256) -> fp32  [profiled slot]
    k_gemm<0,3><<<dim3(NN/128, NN/128, BB), 256, GEMM_SMEM>>>(
        pAph, pApl, pXh, pXl, pS, nullptr, nullptr, pCvec, nullptr,
        DD, NN, NN, (size_t)NN*DD, (size_t)NN*DD, (size_t)NN*NN);
    // 5) softmax -> Ph + 1/l  (vectorized)
    k_softmax<<<ROWS/8, 256>>>();
    // 6) agg = (Ph @ Xth) / l  (K=2048, SINGLE combo) -> fp16 splits
    k_gemm<1,1><<<dim3(NN/128, 2, BB), 256, GEMM_SMEM>>>(
        pPh, nullptr, pXth, nullptr, nullptr, pAggh, pAggl, nullptr, pInvl,
        NN, DD, NN, (size_t)NN*NN, (size_t)DD*NN, (size_t)NN*DD);
    // 7) out = relu(agg @ Wo + bo) -> fp32  (3 combos)
    k_gemm<2,3><<<dim3(ROWS/128, 2, 1), 256, GEMM_SMEM>>>(
        pAggh, pAggl, pWoth, pWotl, out, nullptr, nullptr, bo, nullptr,
        DD, DD, ROWS, 0, 0, 0);
}

// round 10
// speedup vs baseline: 1.2547x; 1.1475x over previous
#include <cuda_runtime.h>
#include <cuda_fp16.h>
#include <cstdint>

#define DD 256
#define BB 16
#define NN 2048
#define ROWS (BB*NN)

typedef __half h16;

// ------------------------------------------------------------------ scratch
__device__ float g_W[DD*DD];                 // Wq @ Wk^T
__device__ float g_u[DD];                    // Wk @ bq
__device__ float g_c[ROWS];                  // X . u  (per key row)
__device__ float g_invl[ROWS];               // 1 / sum(Ph)
__device__ float g_S[(size_t)ROWS*NN];       // scores + c (268MB)

__device__ h16 g_Xh[(size_t)ROWS*DD],  g_Xl[(size_t)ROWS*DD];    // X splits (row-major)
__device__ h16 g_Xth[(size_t)BB*DD*NN];                          // X^T (hi only)
__device__ h16 g_Aph[(size_t)ROWS*DD];                           // A' = X@W (fp16)
__device__ h16 g_Ph[(size_t)ROWS*NN];                            // softmax (hi only)
__device__ h16 g_aggh[(size_t)ROWS*DD], g_aggl[(size_t)ROWS*DD]; // agg splits
__device__ h16 g_Wth[DD*DD], g_Wtl[DD*DD];   // (WqWk^T)^T splits
__device__ h16 g_Woth[DD*DD], g_Wotl[DD*DD]; // Wo^T splits

// ------------------------------------------------------------------ helpers
__device__ __forceinline__ uint32_t smem_u32(const void* p) {
    uint32_t a;
    asm("{ .reg .u64 t; cvta.to.shared.u64 t, %1; cvt.u32.u64 %0, t; }" : "=r"(a) : "l"(p));
    return a;
}
#define CP16(dst, src) \
    asm volatile("cp.async.cg.shared.global [%0], [%1], 16;" :: "r"(dst), "l"(src))
#define CP_COMMIT() asm volatile("cp.async.commit_group;" ::: "memory")
#define CP_WAIT(n)  asm volatile("cp.async.wait_group %0;" :: "n"(n) : "memory")

#define MMA16816(c, a, b)                                                     \
    asm volatile("mma.sync.aligned.m16n8k16.row.col.f32.f16.f16.f32 "         \
        "{%0,%1,%2,%3},{%4,%5,%6,%7},{%8,%9},{%0,%1,%2,%3};"                  \
        : "+f"((c)[0]), "+f"((c)[1]), "+f"((c)[2]), "+f"((c)[3])              \
        : "r"((a)[0]), "r"((a)[1]), "r"((a)[2]), "r"((a)[3]),                 \
          "r"((b)[0]), "r"((b)[1]))

#define LDSM4(r0, r1, r2, r3, addr)                                           \
    asm volatile("ldmatrix.sync.aligned.m8n8.x4.shared.b16 {%0,%1,%2,%3}, [%4];" \
        : "=r"(r0), "=r"(r1), "=r"(r2), "=r"(r3) : "r"(addr))

__device__ __forceinline__ void split2(float f, h16& h, h16& l) {
    h = __float2half_rn(f);
    l = __float2half_rn(f - __half2float(h));
}

// ------------------------------------------------------------------ precompute: W = Wq@Wk^T, u = Wk@bq
__global__ void k_precomp(const float* __restrict__ Wq, const float* __restrict__ Wk,
                          const float* __restrict__ bq) {
    __shared__ float v[DD];
    int bx = blockIdx.x;
    if (bx < DD) {
        v[threadIdx.x] = Wq[bx*DD + threadIdx.x];
        __syncthreads();
        int j = threadIdx.x;
        const float* wk = Wk + j*DD;
        float s = 0.f;
#pragma unroll 8
        for (int e = 0; e < DD; e++) s += v[e] * wk[e];
        g_W[bx*DD + j] = s;
    } else {
        v[threadIdx.x] = bq[threadIdx.x];
        __syncthreads();
        int i = threadIdx.x;
        const float* wk = Wk + i*DD;
        float s = 0.f;
#pragma unroll 8
        for (int e = 0; e < DD; e++) s += wk[e] * v[e];
        g_u[i] = s;
    }
}

// ------------------------------------------------------------------ fused prep
__global__ __launch_bounds__(256) void k_prep(const float* __restrict__ X,
                                              const float* __restrict__ Wo) {
    __shared__ float t[64][65];
    __shared__ float us[DD];
    int bx = blockIdx.x, tid = threadIdx.x;
    if (bx < 512) {
        int which = bx >> 8, j = bx & 255, d = tid;
        const float* src = which ? Wo : g_W;
        h16* dh = which ? g_Woth : g_Wth;
        h16* dl = which ? g_Wotl : g_Wtl;
        float f = src[d*DD + j];
        split2(f, dh[j*DD + d], dl[j*DD + d]);
    } else if (bx < 4608) {
        if (tid < DD) us[tid] = g_u[tid];
        __syncthreads();
        int warp = (bx - 512)*8 + (tid >> 5);
        int lane = tid & 31;
        const float* x = X + (size_t)warp * DD;
        float c = 0.f;
#pragma unroll
        for (int i = 0; i < 8; i++) {
            int e = lane + 32*i;
            float f = x[e];
            c += f * us[e];
            split2(f, g_Xh[(size_t)warp*DD + e], g_Xl[(size_t)warp*DD + e]);
        }
#pragma unroll
        for (int o = 16; o; o >>= 1) c += __shfl_xor_sync(0xffffffffu, c, o);
        if (lane == 0) g_c[warp] = c;
    } else {
        int idx = bx - 4608;
        int n0 = (idx & 31) * 64, d0 = ((idx >> 5) & 3) * 64, b = idx >> 7;
        const float* Xb = X + (size_t)b * NN * DD;
        for (int u = tid; u < 64*16; u += 256) {
            int r = u >> 4, c4 = u & 15;
            float4 v = *(const float4*)(Xb + (size_t)(n0 + r)*DD + d0 + c4*4);
            t[r][c4*4+0] = v.x; t[r][c4*4+1] = v.y; t[r][c4*4+2] = v.z; t[r][c4*4+3] = v.w;
        }
        __syncthreads();
        size_t ob = (size_t)b * DD * NN;
        for (int u = tid; u < 4096; u += 256) {
            int r = u >> 6, c = u & 63;
            g_Xth[ob + (size_t)(d0 + r)*NN + n0 + c] = __float2half_rn(t[c][r]);
        }
    }
}

// warp per row softmax (vectorized; c already folded into S)
__global__ __launch_bounds__(256) void k_softmax() {
    int warp = (blockIdx.x * blockDim.x + threadIdx.x) >> 5;
    int lane = threadIdx.x & 31;
    const float* srow = g_S + (size_t)warp * NN;
    float4 v4[16];
    float mx = -1e30f;
#pragma unroll
    for (int i = 0; i < 16; i++) {
        float4 s = *(const float4*)(srow + i*128 + lane*4);
        v4[i] = s;
        mx = fmaxf(mx, fmaxf(fmaxf(s.x, s.y), fmaxf(s.z, s.w)));
    }
#pragma unroll
    for (int o = 16; o; o >>= 1) mx = fmaxf(mx, __shfl_xor_sync(0xffffffffu, mx, o));
    float sum = 0.f;
    size_t ro = (size_t)warp * NN;
#pragma unroll
    for (int i = 0; i < 16; i++) {
        float e0 = __expf(v4[i].x - mx), e1 = __expf(v4[i].y - mx);
        float e2 = __expf(v4[i].z - mx), e3 = __expf(v4[i].w - mx);
        h16 h0 = __float2half_rn(e0), h1 = __float2half_rn(e1);
        h16 h2 = __float2half_rn(e2), h3 = __float2half_rn(e3);
        sum += __half2float(h0) + __half2float(h1) + __half2float(h2) + __half2float(h3);
        __half2 p01 = __halves2half2(h0, h1), p23 = __halves2half2(h2, h3);
        uint2 pk;
        pk.x = *reinterpret_cast<uint32_t*>(&p01);
        pk.y = *reinterpret_cast<uint32_t*>(&p23);
        *(uint2*)(g_Ph + ro + i*128 + lane*4) = pk;
    }
#pragma unroll
    for (int o = 16; o; o >>= 1) sum += __shfl_xor_sync(0xffffffffu, sum, o);
    if (lane == 0) g_invl[warp] = 1.f / sum;
}

// ------------------------------------------------------------------ HMMA GEMM
// COMBOS: 3 = Ah.Bh + Ah.Bl + Al.Bh   2 = Ah.Bh + Ah.Bl   1 = Ah.Bh
#define TPAD   40
#define TILE_B (128*TPAD*2)       // 10240
#define OFF_AH 0
#define OFF_AL (1*TILE_B)
#define OFF_BH (2*TILE_B)
#define OFF_BL (3*TILE_B)
#define STAGE_B (4*TILE_B)        // 40960
#define GEMM_SMEM (2*STAGE_B)     // 81920 -> two CTAs per SM

// EPI: 0 = fp32 + per-column bias (batch-indexed: c fold)   1 = fp16 split + 1/l scale
//      2 = bias+relu fp32   3 = fp16 hi-only
template<int EPI, int COMBOS>
__global__ __launch_bounds__(256, 2) void k_gemm(
    const h16* __restrict__ Ah, const h16* __restrict__ Al,
    const h16* __restrict__ Bh, const h16* __restrict__ Bl,
    float* __restrict__ Cf, h16* __restrict__ Ch, h16* __restrict__ Cl,
    const float* __restrict__ bias, const float* __restrict__ invl,
    int K, int ldc, int Mrows, size_t sA, size_t sB, size_t sC)
{
    extern __shared__ char smem[];
    uint32_t sb = smem_u32(smem);
    int tid = threadIdx.x;
    int lane = tid & 31, wid = tid >> 5;
    int g = lane >> 2, t = lane & 3;
    int warp_m = (wid & 1) * 64;
    int warp_n = (wid >> 1) * 32;
    int m0 = blockIdx.x * 128, n0 = blockIdx.y * 128, b = blockIdx.z;

    size_t go0 = (size_t)(tid >> 2) * K + (tid & 3) * 8;
    size_t go1 = go0 + (size_t)64 * K;
    uint32_t do0 = (uint32_t)((tid >> 2) * 80 + (tid & 3) * 16);
    uint32_t do1 = do0 + 64*80;

    int lr = ((lane >> 3) & 1) * 8 + (lane & 7);
    int lk = (lane >> 4) * 16;
    uint32_t a_off[4], b_off[2];
#pragma unroll
    for (int i = 0; i < 4; i++) a_off[i] = (uint32_t)((warp_m + i*16 + lr)*80 + lk);
#pragma unroll
    for (int p = 0; p < 2; p++) b_off[p] = (uint32_t)((warp_n + p*16 + lr)*80 + lk);

    const h16* pAh = Ah + (size_t)b*sA + (size_t)m0*K;
    const h16* pAl = (COMBOS >= 3) ? Al + (size_t)b*sA + (size_t)m0*K : nullptr;
    const h16* pBh = Bh + (size_t)b*sB + (size_t)n0*K;
    const h16* pBl = (COMBOS >= 2) ? Bl + (size_t)b*sB + (size_t)n0*K : nullptr;

    // hoisted epilogue scales (PV: 1/l per row) — load before mainloop
    float sc0[4], sc1[4];
    if (EPI == 1 && invl) {
#pragma unroll
        for (int i = 0; i < 4; i++) {
            sc0[i] = invl[(size_t)b*Mrows + m0 + warp_m + i*16 + g];
            sc1[i] = invl[(size_t)b*Mrows + m0 + warp_m + i*16 + g + 8];
        }
    } else {
#pragma unroll
        for (int i = 0; i < 4; i++) { sc0[i] = 1.f; sc1[i] = 1.f; }
    }

    float acc[4][4][4];
#pragma unroll
    for (int i = 0; i < 4; i++)
#pragma unroll
        for (int j = 0; j < 4; j++)
#pragma unroll
            for (int r = 0; r < 4; r++) acc[i][j][r] = 0.f;

#define ISSUE_CHUNK(sbase, k0) do {                                          \
        CP16((sbase) + OFF_AH + do0, pAh + go0 + (k0));                      \
        CP16((sbase) + OFF_AH + do1, pAh + go1 + (k0));                      \
        if (COMBOS >= 3) {                                                   \
            CP16((sbase) + OFF_AL + do0, pAl + go0 + (k0));                  \
            CP16((sbase) + OFF_AL + do1, pAl + go1 + (k0));                  \
        }                                                                    \
        CP16((sbase) + OFF_BH + do0, pBh + go0 + (k0));                      \
        CP16((sbase) + OFF_BH + do1, pBh + go1 + (k0));                      \
        if (COMBOS >= 2) {                                                   \
            CP16((sbase) + OFF_BL + do0, pBl + go0 + (k0));                  \
            CP16((sbase) + OFF_BL + do1, pBl + go1 + (k0));                  \
        }                                                                    \
    } while (0)

    int nchunk = K >> 5;
    ISSUE_CHUNK(sb, 0);
    CP_COMMIT();

    for (int ch = 0; ch < nchunk; ch++) {
        int st = ch & 1;
        if (ch + 1 < nchunk) {
            ISSUE_CHUNK(sb + (uint32_t)(st ^ 1)*STAGE_B, (ch+1) << 5);
            CP_COMMIT();
            CP_WAIT(1);
        } else {
            CP_WAIT(0);
        }
        __syncthreads();

        uint32_t base = sb + (uint32_t)st * STAGE_B;
#pragma unroll
        for (int ks = 0; ks < 2; ks++) {
            uint32_t kb = ks * 32;
            uint32_t ah[4][4], al[4][4], bh[4][2], bl[4][2];
#pragma unroll
            for (int i = 0; i < 4; i++) {
                LDSM4(ah[i][0], ah[i][1], ah[i][2], ah[i][3], base + OFF_AH + a_off[i] + kb);
                if (COMBOS >= 3)
                    LDSM4(al[i][0], al[i][1], al[i][2], al[i][3], base + OFF_AL + a_off[i] + kb);
            }
#pragma unroll
            for (int p = 0; p < 2; p++) {
                LDSM4(bh[2*p][0], bh[2*p+1][0], bh[2*p][1], bh[2*p+1][1],
                      base + OFF_BH + b_off[p] + kb);
                if (COMBOS >= 2)
                    LDSM4(bl[2*p][0], bl[2*p+1][0], bl[2*p][1], bl[2*p+1][1],
                          base + OFF_BL + b_off[p] + kb);
            }
#pragma unroll
            for (int i = 0; i < 4; i++)
#pragma unroll
                for (int j = 0; j < 4; j++) {
                    MMA16816(acc[i][j], ah[i], bh[j]);
                    if (COMBOS >= 2) MMA16816(acc[i][j], ah[i], bl[j]);
                    if (COMBOS >= 3) MMA16816(acc[i][j], al[i], bh[j]);
                }
        }
        __syncthreads();
    }

    // ---- epilogue ----
#pragma unroll
    for (int i = 0; i < 4; i++) {
        int row0 = m0 + warp_m + i*16 + g;
#pragma unroll
        for (int j = 0; j < 4; j++) {
            int col = n0 + warp_n + j*8 + 2*t;
            if (EPI == 0) {
                // S output: add per-column c (bias indexed per batch)
                float c0 = bias[(size_t)b*ldc + col], c1 = bias[(size_t)b*ldc + col + 1];
                float* d0 = Cf + (size_t)b*sC + (size_t)row0*ldc + col;
                float* d1 = d0 + 8*ldc;
                *(float2*)d0 = make_float2(acc[i][j][0] + c0, acc[i][j][1] + c1);
                *(float2*)d1 = make_float2(acc[i][j][2] + c0, acc[i][j][3] + c1);
            } else if (EPI == 1) {
                float v0 = acc[i][j][0]*sc0[i], v1 = acc[i][j][1]*sc0[i];
                float v2 = acc[i][j][2]*sc1[i], v3 = acc[i][j][3]*sc1[i];
                h16 h0, l0, h1, l1, h2, l2, h3, l3;
                split2(v0, h0, l0); split2(v1, h1, l1);
                split2(v2, h2, l2); split2(v3, h3, l3);
                size_t o0 = (size_t)b*sC + (size_t)row0*ldc + col;
                size_t o1 = o0 + 8*(size_t)ldc;
                *(__half2*)(Ch + o0) = __halves2half2(h0, h1);
                *(__half2*)(Ch + o1) = __halves2half2(h2, h3);
                *(__half2*)(Cl + o0) = __halves2half2(l0, l1);
                *(__half2*)(Cl + o1) = __halves2half2(l2, l3);
            } else if (EPI == 3) {
                size_t o0 = (size_t)b*sC + (size_t)row0*ldc + col;
                size_t o1 = o0 + 8*(size_t)ldc;
                *(__half2*)(Ch + o0) = __floats2half2_rn(acc[i][j][0], acc[i][j][1]);
                *(__half2*)(Ch + o1) = __floats2half2_rn(acc[i][j][2], acc[i][j][3]);
            } else {
                float b0 = bias[col], b1 = bias[col+1];
                float* d0 = Cf + (size_t)row0*ldc + col;
                float* d1 = d0 + 8*ldc;
                *(float2*)d0 = make_float2(fmaxf(acc[i][j][0]+b0, 0.f),
                                           fmaxf(acc[i][j][1]+b1, 0.f));
                *(float2*)d1 = make_float2(fmaxf(acc[i][j][2]+b0, 0.f),
                                           fmaxf(acc[i][j][3]+b1, 0.f));
            }
        }
    }
#undef ISSUE_CHUNK
}

// ------------------------------------------------------------------ launch
extern "C" void kernel_launch(void* const* d_in, const int* in_sizes, int n_in,
                              void* d_out, int out_size) {
    const float* inp = (const float*)d_in[0];
    const float* Wq  = (const float*)d_in[1];
    const float* bq  = (const float*)d_in[2];
    const float* Wk  = (const float*)d_in[3];
    // bk (d_in[4]) provably drops out of the softmax — unused.
    const float* Wo  = (const float*)d_in[5];
    const float* bo  = (const float*)d_in[6];
    float* out = (float*)d_out;

    float *pS, *pInvl, *pCvec;
    h16 *pXh, *pXl, *pXth, *pAph, *pPh, *pAggh, *pAggl;
    h16 *pWth, *pWtl, *pWoth, *pWotl;
    cudaGetSymbolAddress((void**)&pS, g_S);
    cudaGetSymbolAddress((void**)&pInvl, g_invl);
    cudaGetSymbolAddress((void**)&pCvec, g_c);
    cudaGetSymbolAddress((void**)&pXh, g_Xh);   cudaGetSymbolAddress((void**)&pXl, g_Xl);
    cudaGetSymbolAddress((void**)&pXth, g_Xth);
    cudaGetSymbolAddress((void**)&pAph, g_Aph);
    cudaGetSymbolAddress((void**)&pPh, g_Ph);
    cudaGetSymbolAddress((void**)&pAggh, g_aggh); cudaGetSymbolAddress((void**)&pAggl, g_aggl);
    cudaGetSymbolAddress((void**)&pWth, g_Wth); cudaGetSymbolAddress((void**)&pWtl, g_Wtl);
    cudaGetSymbolAddress((void**)&pWoth, g_Woth); cudaGetSymbolAddress((void**)&pWotl, g_Wotl);

    cudaFuncSetAttribute((const void*)k_gemm<3,3>, cudaFuncAttributeMaxDynamicSharedMemorySize, GEMM_SMEM);
    cudaFuncSetAttribute((const void*)k_gemm<0,2>, cudaFuncAttributeMaxDynamicSharedMemorySize, GEMM_SMEM);
    cudaFuncSetAttribute((const void*)k_gemm<1,1>, cudaFuncAttributeMaxDynamicSharedMemorySize, GEMM_SMEM);
    cudaFuncSetAttribute((const void*)k_gemm<2,3>, cudaFuncAttributeMaxDynamicSharedMemorySize, GEMM_SMEM);

    // 1) W = Wq Wk^T, u = Wk bq
    k_precomp<<<DD + 1, DD>>>(Wq, Wk, bq);
    // 2) all splits/transposes + c
    k_prep<<<6656, 256>>>(inp, Wo);
    // 3) A' = X @ W -> fp16 (hi only; 3 combos for accuracy)
    k_gemm<3,3><<<dim3(ROWS/128, 2, 1), 256, GEMM_SMEM>>>(
        pXh, pXl, pWth, pWtl, nullptr, pAph, nullptr, nullptr, nullptr,
        DD, DD, ROWS, 0, 0, 0);
    // 4) S = A' @ X^T + c  (2 combos: Ah.Bh + Ah.Bl) -> fp32  [profiled slot]
    k_gemm<0,2><<<dim3(NN/128, NN/128, BB), 256, GEMM_SMEM>>>(
        pAph, nullptr, pXh, pXl, pS, nullptr, nullptr, pCvec, nullptr,
        DD, NN, NN, (size_t)NN*DD, (size_t)NN*DD, (size_t)NN*NN);
    // 5) softmax -> Ph + 1/l  (vectorized)
    k_softmax<<<ROWS/8, 256>>>();
    // 6) agg = (Ph @ Xth) / l  (K=2048, single combo) -> fp16 splits
    k_gemm<1,1><<<dim3(NN/128, 2, BB), 256, GEMM_SMEM>>>(
        pPh, nullptr, pXth, nullptr, nullptr, pAggh, pAggl, nullptr, pInvl,
        NN, DD, NN, (size_t)NN*NN, (size_t)DD*NN, (size_t)NN*DD);
    // 7) out = relu(agg @ Wo + bo) -> fp32  (3 combos)
    k_gemm<2,3><<<dim3(ROWS/128, 2, 1), 256, GEMM_SMEM>>>(
        pAggh, pAggl, pWoth, pWotl, out, nullptr, nullptr, bo, nullptr,
        DD, DD, ROWS, 0, 0, 0);
}

// round 11
// speedup vs baseline: 1.3487x; 1.0749x over previous
#include <cuda_runtime.h>
#include <cuda_fp16.h>
#include <cstdint>

#define DD 256
#define BB 16
#define NN 2048
#define ROWS (BB*NN)

typedef __half h16;

// ------------------------------------------------------------------ scratch
__device__ float g_W[DD*DD];                 // Wq @ Wk^T
__device__ float g_u[DD];                    // Wk @ bq
__device__ float g_c[ROWS];                  // X . u  (per key row)
__device__ float g_invl[ROWS];               // 1 / sum(Ph)
__device__ float g_S[(size_t)ROWS*NN];       // scores + c (268MB)

__device__ h16 g_Xh[(size_t)ROWS*DD],  g_Xl[(size_t)ROWS*DD];    // X splits (row-major)
__device__ h16 g_Xth[(size_t)BB*DD*NN];                          // X^T (hi only)
__device__ h16 g_Aph[(size_t)ROWS*DD];                           // A' = X@W (fp16)
__device__ h16 g_Ph[(size_t)ROWS*NN];                            // softmax (hi only)
__device__ h16 g_aggh[(size_t)ROWS*DD], g_aggl[(size_t)ROWS*DD]; // agg splits
__device__ h16 g_Wth[DD*DD], g_Wtl[DD*DD];   // (WqWk^T)^T splits
__device__ h16 g_Woth[DD*DD], g_Wotl[DD*DD]; // Wo^T splits

// ------------------------------------------------------------------ helpers
__device__ __forceinline__ uint32_t smem_u32(const void* p) {
    uint32_t a;
    asm("{ .reg .u64 t; cvta.to.shared.u64 t, %1; cvt.u32.u64 %0, t; }" : "=r"(a) : "l"(p));
    return a;
}
#define CP16(dst, src) \
    asm volatile("cp.async.cg.shared.global [%0], [%1], 16;" :: "r"(dst), "l"(src))
#define CP_COMMIT() asm volatile("cp.async.commit_group;" ::: "memory")
#define CP_WAIT(n)  asm volatile("cp.async.wait_group %0;" :: "n"(n) : "memory")

#define MMA16816(c, a, b)                                                     \
    asm volatile("mma.sync.aligned.m16n8k16.row.col.f32.f16.f16.f32 "         \
        "{%0,%1,%2,%3},{%4,%5,%6,%7},{%8,%9},{%0,%1,%2,%3};"                  \
        : "+f"((c)[0]), "+f"((c)[1]), "+f"((c)[2]), "+f"((c)[3])              \
        : "r"((a)[0]), "r"((a)[1]), "r"((a)[2]), "r"((a)[3]),                 \
          "r"((b)[0]), "r"((b)[1]))

#define LDSM4(r0, r1, r2, r3, addr)                                           \
    asm volatile("ldmatrix.sync.aligned.m8n8.x4.shared.b16 {%0,%1,%2,%3}, [%4];" \
        : "=r"(r0), "=r"(r1), "=r"(r2), "=r"(r3) : "r"(addr))

__device__ __forceinline__ void split2(float f, h16& h, h16& l) {
    h = __float2half_rn(f);
    l = __float2half_rn(f - __half2float(h));
}

// ------------------------------------------------------------------ precompute: W = Wq@Wk^T, u = Wk@bq
__global__ void k_precomp(const float* __restrict__ Wq, const float* __restrict__ Wk,
                          const float* __restrict__ bq) {
    __shared__ float v[DD];
    int bx = blockIdx.x;
    if (bx < DD) {
        v[threadIdx.x] = Wq[bx*DD + threadIdx.x];
        __syncthreads();
        int j = threadIdx.x;
        const float* wk = Wk + j*DD;
        float s = 0.f;
#pragma unroll 8
        for (int e = 0; e < DD; e++) s += v[e] * wk[e];
        g_W[bx*DD + j] = s;
    } else {
        v[threadIdx.x] = bq[threadIdx.x];
        __syncthreads();
        int i = threadIdx.x;
        const float* wk = Wk + i*DD;
        float s = 0.f;
#pragma unroll 8
        for (int e = 0; e < DD; e++) s += wk[e] * v[e];
        g_u[i] = s;
    }
}

// ------------------------------------------------------------------ fused prep
__global__ __launch_bounds__(256) void k_prep(const float* __restrict__ X,
                                              const float* __restrict__ Wo) {
    __shared__ float t[64][65];
    __shared__ float us[DD];
    int bx = blockIdx.x, tid = threadIdx.x;
    if (bx < 512) {
        int which = bx >> 8, j = bx & 255, d = tid;
        const float* src = which ? Wo : g_W;
        h16* dh = which ? g_Woth : g_Wth;
        h16* dl = which ? g_Wotl : g_Wtl;
        float f = src[d*DD + j];
        split2(f, dh[j*DD + d], dl[j*DD + d]);
    } else if (bx < 4608) {
        if (tid < DD) us[tid] = g_u[tid];
        __syncthreads();
        int warp = (bx - 512)*8 + (tid >> 5);
        int lane = tid & 31;
        const float* x = X + (size_t)warp * DD;
        float c = 0.f;
#pragma unroll
        for (int i = 0; i < 8; i++) {
            int e = lane + 32*i;
            float f = x[e];
            c += f * us[e];
            split2(f, g_Xh[(size_t)warp*DD + e], g_Xl[(size_t)warp*DD + e]);
        }
#pragma unroll
        for (int o = 16; o; o >>= 1) c += __shfl_xor_sync(0xffffffffu, c, o);
        if (lane == 0) g_c[warp] = c;
    } else {
        int idx = bx - 4608;
        int n0 = (idx & 31) * 64, d0 = ((idx >> 5) & 3) * 64, b = idx >> 7;
        const float* Xb = X + (size_t)b * NN * DD;
        for (int u = tid; u < 64*16; u += 256) {
            int r = u >> 4, c4 = u & 15;
            float4 v = *(const float4*)(Xb + (size_t)(n0 + r)*DD + d0 + c4*4);
            t[r][c4*4+0] = v.x; t[r][c4*4+1] = v.y; t[r][c4*4+2] = v.z; t[r][c4*4+3] = v.w;
        }
        __syncthreads();
        size_t ob = (size_t)b * DD * NN;
        for (int u = tid; u < 4096; u += 256) {
            int r = u >> 6, c = u & 63;
            g_Xth[ob + (size_t)(d0 + r)*NN + n0 + c] = __float2half_rn(t[c][r]);
        }
    }
}

// warp per row softmax (vectorized; c already folded into S)
__global__ __launch_bounds__(256) void k_softmax() {
    int warp = (blockIdx.x * blockDim.x + threadIdx.x) >> 5;
    int lane = threadIdx.x & 31;
    const float* srow = g_S + (size_t)warp * NN;
    float4 v4[16];
    float mx = -1e30f;
#pragma unroll
    for (int i = 0; i < 16; i++) {
        float4 s = *(const float4*)(srow + i*128 + lane*4);
        v4[i] = s;
        mx = fmaxf(mx, fmaxf(fmaxf(s.x, s.y), fmaxf(s.z, s.w)));
    }
#pragma unroll
    for (int o = 16; o; o >>= 1) mx = fmaxf(mx, __shfl_xor_sync(0xffffffffu, mx, o));
    float sum = 0.f;
    size_t ro = (size_t)warp * NN;
#pragma unroll
    for (int i = 0; i < 16; i++) {
        float e0 = __expf(v4[i].x - mx), e1 = __expf(v4[i].y - mx);
        float e2 = __expf(v4[i].z - mx), e3 = __expf(v4[i].w - mx);
        h16 h0 = __float2half_rn(e0), h1 = __float2half_rn(e1);
        h16 h2 = __float2half_rn(e2), h3 = __float2half_rn(e3);
        sum += __half2float(h0) + __half2float(h1) + __half2float(h2) + __half2float(h3);
        __half2 p01 = __halves2half2(h0, h1), p23 = __halves2half2(h2, h3);
        uint2 pk;
        pk.x = *reinterpret_cast<uint32_t*>(&p01);
        pk.y = *reinterpret_cast<uint32_t*>(&p23);
        *(uint2*)(g_Ph + ro + i*128 + lane*4) = pk;
    }
#pragma unroll
    for (int o = 16; o; o >>= 1) sum += __shfl_xor_sync(0xffffffffu, sum, o);
    if (lane == 0) g_invl[warp] = 1.f / sum;
}

// ------------------------------------------------------------------ HMMA GEMM (32-K chunks, 3-combo small GEMMs)
#define TPAD   40
#define TILE_B (128*TPAD*2)       // 10240
#define OFF_AH 0
#define OFF_AL (1*TILE_B)
#define OFF_BH (2*TILE_B)
#define OFF_BL (3*TILE_B)
#define STAGE_B (4*TILE_B)        // 40960
#define GEMM_SMEM (2*STAGE_B)     // 81920

// EPI: 2 = bias+relu fp32   3 = fp16 hi-only
template<int EPI, int COMBOS>
__global__ __launch_bounds__(256, 2) void k_gemm(
    const h16* __restrict__ Ah, const h16* __restrict__ Al,
    const h16* __restrict__ Bh, const h16* __restrict__ Bl,
    float* __restrict__ Cf, h16* __restrict__ Ch, h16* __restrict__ Cl,
    const float* __restrict__ bias, const float* __restrict__ invl,
    int K, int ldc, int Mrows, size_t sA, size_t sB, size_t sC)
{
    extern __shared__ char smem[];
    uint32_t sb = smem_u32(smem);
    int tid = threadIdx.x;
    int lane = tid & 31, wid = tid >> 5;
    int g = lane >> 2, t = lane & 3;
    int warp_m = (wid & 1) * 64;
    int warp_n = (wid >> 1) * 32;
    int m0 = blockIdx.x * 128, n0 = blockIdx.y * 128, b = blockIdx.z;

    size_t go0 = (size_t)(tid >> 2) * K + (tid & 3) * 8;
    size_t go1 = go0 + (size_t)64 * K;
    uint32_t do0 = (uint32_t)((tid >> 2) * 80 + (tid & 3) * 16);
    uint32_t do1 = do0 + 64*80;

    int lr = ((lane >> 3) & 1) * 8 + (lane & 7);
    int lk = (lane >> 4) * 16;
    uint32_t a_off[4], b_off[2];
#pragma unroll
    for (int i = 0; i < 4; i++) a_off[i] = (uint32_t)((warp_m + i*16 + lr)*80 + lk);
#pragma unroll
    for (int p = 0; p < 2; p++) b_off[p] = (uint32_t)((warp_n + p*16 + lr)*80 + lk);

    const h16* pAh = Ah + (size_t)b*sA + (size_t)m0*K;
    const h16* pAl = (COMBOS >= 3) ? Al + (size_t)b*sA + (size_t)m0*K : nullptr;
    const h16* pBh = Bh + (size_t)b*sB + (size_t)n0*K;
    const h16* pBl = (COMBOS >= 2) ? Bl + (size_t)b*sB + (size_t)n0*K : nullptr;

    float acc[4][4][4];
#pragma unroll
    for (int i = 0; i < 4; i++)
#pragma unroll
        for (int j = 0; j < 4; j++)
#pragma unroll
            for (int r = 0; r < 4; r++) acc[i][j][r] = 0.f;

#define ISSUE_CHUNK(sbase, k0) do {                                          \
        CP16((sbase) + OFF_AH + do0, pAh + go0 + (k0));                      \
        CP16((sbase) + OFF_AH + do1, pAh + go1 + (k0));                      \
        if (COMBOS >= 3) {                                                   \
            CP16((sbase) + OFF_AL + do0, pAl + go0 + (k0));                  \
            CP16((sbase) + OFF_AL + do1, pAl + go1 + (k0));                  \
        }                                                                    \
        CP16((sbase) + OFF_BH + do0, pBh + go0 + (k0));                      \
        CP16((sbase) + OFF_BH + do1, pBh + go1 + (k0));                      \
        if (COMBOS >= 2) {                                                   \
            CP16((sbase) + OFF_BL + do0, pBl + go0 + (k0));                  \
            CP16((sbase) + OFF_BL + do1, pBl + go1 + (k0));                  \
        }                                                                    \
    } while (0)

    int nchunk = K >> 5;
    ISSUE_CHUNK(sb, 0);
    CP_COMMIT();

    for (int ch = 0; ch < nchunk; ch++) {
        int st = ch & 1;
        if (ch + 1 < nchunk) {
            ISSUE_CHUNK(sb + (uint32_t)(st ^ 1)*STAGE_B, (ch+1) << 5);
            CP_COMMIT();
            CP_WAIT(1);
        } else {
            CP_WAIT(0);
        }
        __syncthreads();

        uint32_t base = sb + (uint32_t)st * STAGE_B;
#pragma unroll
        for (int ks = 0; ks < 2; ks++) {
            uint32_t kb = ks * 32;
            uint32_t ah[4][4], al[4][4], bh[4][2], bl[4][2];
#pragma unroll
            for (int i = 0; i < 4; i++) {
                LDSM4(ah[i][0], ah[i][1], ah[i][2], ah[i][3], base + OFF_AH + a_off[i] + kb);
                if (COMBOS >= 3)
                    LDSM4(al[i][0], al[i][1], al[i][2], al[i][3], base + OFF_AL + a_off[i] + kb);
            }
#pragma unroll
            for (int p = 0; p < 2; p++) {
                LDSM4(bh[2*p][0], bh[2*p+1][0], bh[2*p][1], bh[2*p+1][1],
                      base + OFF_BH + b_off[p] + kb);
                if (COMBOS >= 2)
                    LDSM4(bl[2*p][0], bl[2*p+1][0], bl[2*p][1], bl[2*p+1][1],
                          base + OFF_BL + b_off[p] + kb);
            }
#pragma unroll
            for (int i = 0; i < 4; i++)
#pragma unroll
                for (int j = 0; j < 4; j++) {
                    MMA16816(acc[i][j], ah[i], bh[j]);
                    if (COMBOS >= 2) MMA16816(acc[i][j], ah[i], bl[j]);
                    if (COMBOS >= 3) MMA16816(acc[i][j], al[i], bh[j]);
                }
        }
        __syncthreads();
    }

#pragma unroll
    for (int i = 0; i < 4; i++) {
        int row0 = m0 + warp_m + i*16 + g;
#pragma unroll
        for (int j = 0; j < 4; j++) {
            int col = n0 + warp_n + j*8 + 2*t;
            if (EPI == 3) {
                size_t o0 = (size_t)b*sC + (size_t)row0*ldc + col;
                size_t o1 = o0 + 8*(size_t)ldc;
                *(__half2*)(Ch + o0) = __floats2half2_rn(acc[i][j][0], acc[i][j][1]);
                *(__half2*)(Ch + o1) = __floats2half2_rn(acc[i][j][2], acc[i][j][3]);
            } else {
                float b0 = bias[col], b1 = bias[col+1];
                float* d0 = Cf + (size_t)row0*ldc + col;
                float* d1 = d0 + 8*ldc;
                *(float2*)d0 = make_float2(fmaxf(acc[i][j][0]+b0, 0.f),
                                           fmaxf(acc[i][j][1]+b1, 0.f));
                *(float2*)d1 = make_float2(fmaxf(acc[i][j][2]+b0, 0.f),
                                           fmaxf(acc[i][j][3]+b1, 0.f));
            }
        }
    }
#undef ISSUE_CHUNK
}

// ------------------------------------------------------------------ HMMA GEMM, 64-K chunks (big GEMMs)
// Row stride 144B (64 data + 8 pad halfs): ldmatrix conflict-free (stride = 4 words mod 32).
#define T64_B  (128*144)          // 18432 per tile

// EPI: 0 = fp32 + per-column batch-indexed bias (c fold)   1 = fp16 split + 1/l scale
// COMBOS: 2 = Ah.Bh + Ah.Bl   1 = Ah.Bh
template<int EPI, int COMBOS>
__global__ __launch_bounds__(256, 2) void k_gemm64(
    const h16* __restrict__ Ah,
    const h16* __restrict__ Bh, const h16* __restrict__ Bl,
    float* __restrict__ Cf, h16* __restrict__ Ch, h16* __restrict__ Cl,
    const float* __restrict__ bias, const float* __restrict__ invl,
    int K, int ldc, int Mrows, size_t sA, size_t sB, size_t sC)
{
    constexpr uint32_t OFF_A = 0;
    constexpr uint32_t OFF_B = T64_B;
    constexpr uint32_t OFF_B2 = 2*T64_B;
    constexpr uint32_t STAGE = (COMBOS >= 2 ? 3 : 2) * T64_B;

    extern __shared__ char smem[];
    uint32_t sb = smem_u32(smem);
    int tid = threadIdx.x;
    int lane = tid & 31, wid = tid >> 5;
    int g = lane >> 2, t = lane & 3;
    int warp_m = (wid & 1) * 64;
    int warp_n = (wid >> 1) * 32;
    int m0 = blockIdx.x * 128, n0 = blockIdx.y * 128, b = blockIdx.z;

    // per-thread cp.async offsets: row = tid>>3 (+32 per pass), seg = tid&7
    size_t gob = (size_t)(tid >> 3) * K + (tid & 7) * 8;
    uint32_t dob = (uint32_t)((tid >> 3) * 144 + (tid & 7) * 16);

    int lr = ((lane >> 3) & 1) * 8 + (lane & 7);
    int lk = (lane >> 4) * 16;
    uint32_t a_off[4], b_off[2];
#pragma unroll
    for (int i = 0; i < 4; i++) a_off[i] = (uint32_t)((warp_m + i*16 + lr)*144 + lk);
#pragma unroll
    for (int p = 0; p < 2; p++) b_off[p] = (uint32_t)((warp_n + p*16 + lr)*144 + lk);

    const h16* pAh = Ah + (size_t)b*sA + (size_t)m0*K;
    const h16* pBh = Bh + (size_t)b*sB + (size_t)n0*K;
    const h16* pBl = (COMBOS >= 2) ? Bl + (size_t)b*sB + (size_t)n0*K : nullptr;

    // hoisted epilogue scales (PV: 1/l per row)
    float sc0[4], sc1[4];
    if (EPI == 1 && invl) {
#pragma unroll
        for (int i = 0; i < 4; i++) {
            sc0[i] = invl[(size_t)b*Mrows + m0 + warp_m + i*16 + g];
            sc1[i] = invl[(size_t)b*Mrows + m0 + warp_m + i*16 + g + 8];
        }
    } else {
#pragma unroll
        for (int i = 0; i < 4; i++) { sc0[i] = 1.f; sc1[i] = 1.f; }
    }

    float acc[4][4][4];
#pragma unroll
    for (int i = 0; i < 4; i++)
#pragma unroll
        for (int j = 0; j < 4; j++)
#pragma unroll
            for (int r = 0; r < 4; r++) acc[i][j][r] = 0.f;

#define ISSUE64(sbase, k0) do {                                              \
        _Pragma("unroll")                                                    \
        for (int _i = 0; _i < 4; _i++) {                                     \
            size_t _g = gob + (size_t)(32*_i)*K + (k0);                      \
            uint32_t _d = dob + 32*_i*144;                                   \
            CP16((sbase) + OFF_A + _d, pAh + _g);                            \
            CP16((sbase) + OFF_B + _d, pBh + _g);                            \
            if (COMBOS >= 2) CP16((sbase) + OFF_B2 + _d, pBl + _g);          \
        }                                                                    \
    } while (0)

    int nchunk = K >> 6;
    ISSUE64(sb, 0);
    CP_COMMIT();

    for (int ch = 0; ch < nchunk; ch++) {
        int st = ch & 1;
        if (ch + 1 < nchunk) {
            ISSUE64(sb + (uint32_t)(st ^ 1)*STAGE, (ch+1) << 6);
            CP_COMMIT();
            CP_WAIT(1);
        } else {
            CP_WAIT(0);
        }
        __syncthreads();

        uint32_t base = sb + (uint32_t)st * STAGE;
#pragma unroll
        for (int ks = 0; ks < 4; ks++) {
            uint32_t kb = ks * 32;
            uint32_t ah[4][4], bh[4][2], bl[4][2];
#pragma unroll
            for (int i = 0; i < 4; i++)
                LDSM4(ah[i][0], ah[i][1], ah[i][2], ah[i][3], base + OFF_A + a_off[i] + kb);
#pragma unroll
            for (int p = 0; p < 2; p++) {
                LDSM4(bh[2*p][0], bh[2*p+1][0], bh[2*p][1], bh[2*p+1][1],
                      base + OFF_B + b_off[p] + kb);
                if (COMBOS >= 2)
                    LDSM4(bl[2*p][0], bl[2*p+1][0], bl[2*p][1], bl[2*p+1][1],
                          base + OFF_B2 + b_off[p] + kb);
            }
#pragma unroll
            for (int i = 0; i < 4; i++)
#pragma unroll
                for (int j = 0; j < 4; j++) {
                    MMA16816(acc[i][j], ah[i], bh[j]);
                    if (COMBOS >= 2) MMA16816(acc[i][j], ah[i], bl[j]);
                }
        }
        __syncthreads();
    }

    // ---- epilogue ----
#pragma unroll
    for (int i = 0; i < 4; i++) {
        int row0 = m0 + warp_m + i*16 + g;
#pragma unroll
        for (int j = 0; j < 4; j++) {
            int col = n0 + warp_n + j*8 + 2*t;
            if (EPI == 0) {
                float c0 = bias[(size_t)b*ldc + col], c1 = bias[(size_t)b*ldc + col + 1];
                float* d0 = Cf + (size_t)b*sC + (size_t)row0*ldc + col;
                float* d1 = d0 + 8*ldc;
                *(float2*)d0 = make_float2(acc[i][j][0] + c0, acc[i][j][1] + c1);
                *(float2*)d1 = make_float2(acc[i][j][2] + c0, acc[i][j][3] + c1);
            } else {
                float v0 = acc[i][j][0]*sc0[i], v1 = acc[i][j][1]*sc0[i];
                float v2 = acc[i][j][2]*sc1[i], v3 = acc[i][j][3]*sc1[i];
                h16 h0, l0, h1, l1, h2, l2, h3, l3;
                split2(v0, h0, l0); split2(v1, h1, l1);
                split2(v2, h2, l2); split2(v3, h3, l3);
                size_t o0 = (size_t)b*sC + (size_t)row0*ldc + col;
                size_t o1 = o0 + 8*(size_t)ldc;
                *(__half2*)(Ch + o0) = __halves2half2(h0, h1);
                *(__half2*)(Ch + o1) = __halves2half2(h2, h3);
                *(__half2*)(Cl + o0) = __halves2half2(l0, l1);
                *(__half2*)(Cl + o1) = __halves2half2(l2, l3);
            }
        }
    }
#undef ISSUE64
}

#define S_SMEM   (2*3*T64_B)   // 110592
#define PV_SMEM  (2*2*T64_B)   // 73728

// ------------------------------------------------------------------ launch
extern "C" void kernel_launch(void* const* d_in, const int* in_sizes, int n_in,
                              void* d_out, int out_size) {
    const float* inp = (const float*)d_in[0];
    const float* Wq  = (const float*)d_in[1];
    const float* bq  = (const float*)d_in[2];
    const float* Wk  = (const float*)d_in[3];
    // bk (d_in[4]) provably drops out of the softmax — unused.
    const float* Wo  = (const float*)d_in[5];
    const float* bo  = (const float*)d_in[6];
    float* out = (float*)d_out;

    float *pS, *pInvl, *pCvec;
    h16 *pXh, *pXl, *pXth, *pAph, *pPh, *pAggh, *pAggl;
    h16 *pWth, *pWtl, *pWoth, *pWotl;
    cudaGetSymbolAddress((void**)&pS, g_S);
    cudaGetSymbolAddress((void**)&pInvl, g_invl);
    cudaGetSymbolAddress((void**)&pCvec, g_c);
    cudaGetSymbolAddress((void**)&pXh, g_Xh);   cudaGetSymbolAddress((void**)&pXl, g_Xl);
    cudaGetSymbolAddress((void**)&pXth, g_Xth);
    cudaGetSymbolAddress((void**)&pAph, g_Aph);
    cudaGetSymbolAddress((void**)&pPh, g_Ph);
    cudaGetSymbolAddress((void**)&pAggh, g_aggh); cudaGetSymbolAddress((void**)&pAggl, g_aggl);
    cudaGetSymbolAddress((void**)&pWth, g_Wth); cudaGetSymbolAddress((void**)&pWtl, g_Wtl);
    cudaGetSymbolAddress((void**)&pWoth, g_Woth); cudaGetSymbolAddress((void**)&pWotl, g_Wotl);

    cudaFuncSetAttribute((const void*)k_gemm<3,3>,   cudaFuncAttributeMaxDynamicSharedMemorySize, GEMM_SMEM);
    cudaFuncSetAttribute((const void*)k_gemm<2,3>,   cudaFuncAttributeMaxDynamicSharedMemorySize, GEMM_SMEM);
    cudaFuncSetAttribute((const void*)k_gemm64<0,2>, cudaFuncAttributeMaxDynamicSharedMemorySize, S_SMEM);
    cudaFuncSetAttribute((const void*)k_gemm64<1,1>, cudaFuncAttributeMaxDynamicSharedMemorySize, PV_SMEM);

    // 1) W = Wq Wk^T, u = Wk bq
    k_precomp<<<DD + 1, DD>>>(Wq, Wk, bq);
    // 2) all splits/transposes + c
    k_prep<<<6656, 256>>>(inp, Wo);
    // 3) A' = X @ W -> fp16 (hi only; 3 combos for accuracy)
    k_gemm<3,3><<<dim3(ROWS/128, 2, 1), 256, GEMM_SMEM>>>(
        pXh, pXl, pWth, pWtl, nullptr, pAph, nullptr, nullptr, nullptr,
        DD, DD, ROWS, 0, 0, 0);
    // 4) S = A' @ X^T + c  (2 combos, 64-K chunks) -> fp32  [profiled slot]
    k_gemm64<0,2><<<dim3(NN/128, NN/128, BB), 256, S_SMEM>>>(
        pAph, pXh, pXl, pS, nullptr, nullptr, pCvec, nullptr,
        DD, NN, NN, (size_t)NN*DD, (size_t)NN*DD, (size_t)NN*NN);
    // 5) softmax -> Ph + 1/l  (vectorized)
    k_softmax<<<ROWS/8, 256>>>();
    // 6) agg = (Ph @ Xth) / l  (K=2048, 1 combo, 64-K chunks) -> fp16 splits
    k_gemm64<1,1><<<dim3(NN/128, 2, BB), 256, PV_SMEM>>>(
        pPh, pXth, nullptr, nullptr, pAggh, pAggl, nullptr, pInvl,
        NN, DD, NN, (size_t)NN*NN, (size_t)DD*NN, (size_t)NN*DD);
    // 7) out = relu(agg @ Wo + bo) -> fp32  (3 combos)
    k_gemm<2,3><<<dim3(ROWS/128, 2, 1), 256, GEMM_SMEM>>>(
        pAggh, pAggl, pWoth, pWotl, out, nullptr, nullptr, bo, nullptr,
        DD, DD, ROWS, 0, 0, 0);
}

// round 12
// speedup vs baseline: 1.3633x; 1.0108x over previous
#include <cuda_runtime.h>
#include <cuda_fp16.h>
#include <cstdint>

#define DD 256
#define BB 16
#define NN 2048
#define ROWS (BB*NN)

typedef __half h16;

// ------------------------------------------------------------------ scratch
__device__ float g_W[DD*DD];                 // Wq @ Wk^T
__device__ float g_u[DD];                    // Wk @ bq
__device__ float g_c[ROWS];                  // X . u  (per key row)
__device__ float g_invl[ROWS];               // 1 / sum(Ph)
__device__ float g_S[(size_t)ROWS*NN];       // scores + c (268MB)

__device__ h16 g_Xh[(size_t)ROWS*DD],  g_Xl[(size_t)ROWS*DD];    // X splits (row-major)
__device__ h16 g_Xth[(size_t)BB*DD*NN];                          // X^T (hi only)
__device__ h16 g_Aph[(size_t)ROWS*DD];                           // A' = X@W (fp16)
__device__ h16 g_Ph[(size_t)ROWS*NN];                            // softmax (hi only)
__device__ h16 g_aggh[(size_t)ROWS*DD], g_aggl[(size_t)ROWS*DD]; // agg splits
__device__ h16 g_Wth[DD*DD], g_Wtl[DD*DD];   // (WqWk^T)^T splits
__device__ h16 g_Woth[DD*DD], g_Wotl[DD*DD]; // Wo^T splits

// ------------------------------------------------------------------ helpers
__device__ __forceinline__ uint32_t smem_u32(const void* p) {
    uint32_t a;
    asm("{ .reg .u64 t; cvta.to.shared.u64 t, %1; cvt.u32.u64 %0, t; }" : "=r"(a) : "l"(p));
    return a;
}
#define CP16(dst, src) \
    asm volatile("cp.async.cg.shared.global [%0], [%1], 16;" :: "r"(dst), "l"(src))
#define CP_COMMIT() asm volatile("cp.async.commit_group;" ::: "memory")
#define CP_WAIT(n)  asm volatile("cp.async.wait_group %0;" :: "n"(n) : "memory")

#define MMA16816(c, a, b)                                                     \
    asm volatile("mma.sync.aligned.m16n8k16.row.col.f32.f16.f16.f32 "         \
        "{%0,%1,%2,%3},{%4,%5,%6,%7},{%8,%9},{%0,%1,%2,%3};"                  \
        : "+f"((c)[0]), "+f"((c)[1]), "+f"((c)[2]), "+f"((c)[3])              \
        : "r"((a)[0]), "r"((a)[1]), "r"((a)[2]), "r"((a)[3]),                 \
          "r"((b)[0]), "r"((b)[1]))

#define LDSM4(r0, r1, r2, r3, addr)                                           \
    asm volatile("ldmatrix.sync.aligned.m8n8.x4.shared.b16 {%0,%1,%2,%3}, [%4];" \
        : "=r"(r0), "=r"(r1), "=r"(r2), "=r"(r3) : "r"(addr))

__device__ __forceinline__ void split2(float f, h16& h, h16& l) {
    h = __float2half_rn(f);
    l = __float2half_rn(f - __half2float(h));
}

// FFMA-pipe exp for y <= 0: 2^(y*log2e), degree-6 Taylor on fractional part.
// rel err <= ~1.6e-5 (far below the fp16 rounding applied to the result).
__device__ __forceinline__ float fexp(float y) {
    float t = y * 1.4426950408889634f;
    int i = __float2int_rd(t);
    float f = t - (float)i;
    float p = 1.5403530e-4f;
    p = fmaf(p, f, 1.3333558e-3f);
    p = fmaf(p, f, 9.6181291e-3f);
    p = fmaf(p, f, 5.5504109e-2f);
    p = fmaf(p, f, 2.4022651e-1f);
    p = fmaf(p, f, 6.9314718e-1f);
    p = fmaf(p, f, 1.0f);
    i = (i < -126) ? -126 : i;
    return p * __int_as_float((uint32_t)(i + 127) << 23);
}

// ------------------------------------------------------------------ precompute: W = Wq@Wk^T, u = Wk@bq
__global__ void k_precomp(const float* __restrict__ Wq, const float* __restrict__ Wk,
                          const float* __restrict__ bq) {
    __shared__ float v[DD];
    int bx = blockIdx.x;
    if (bx < DD) {
        v[threadIdx.x] = Wq[bx*DD + threadIdx.x];
        __syncthreads();
        int j = threadIdx.x;
        const float* wk = Wk + j*DD;
        float s = 0.f;
#pragma unroll 8
        for (int e = 0; e < DD; e++) s += v[e] * wk[e];
        g_W[bx*DD + j] = s;
    } else {
        v[threadIdx.x] = bq[threadIdx.x];
        __syncthreads();
        int i = threadIdx.x;
        const float* wk = Wk + i*DD;
        float s = 0.f;
#pragma unroll 8
        for (int e = 0; e < DD; e++) s += wk[e] * v[e];
        g_u[i] = s;
    }
}

// ------------------------------------------------------------------ fused prep
__global__ __launch_bounds__(256) void k_prep(const float* __restrict__ X,
                                              const float* __restrict__ Wo) {
    __shared__ float t[64][65];
    __shared__ float us[DD];
    int bx = blockIdx.x, tid = threadIdx.x;
    if (bx < 512) {
        int which = bx >> 8, j = bx & 255, d = tid;
        const float* src = which ? Wo : g_W;
        h16* dh = which ? g_Woth : g_Wth;
        h16* dl = which ? g_Wotl : g_Wtl;
        float f = src[d*DD + j];
        split2(f, dh[j*DD + d], dl[j*DD + d]);
    } else if (bx < 4608) {
        if (tid < DD) us[tid] = g_u[tid];
        __syncthreads();
        int warp = (bx - 512)*8 + (tid >> 5);
        int lane = tid & 31;
        const float* x = X + (size_t)warp * DD;
        float c = 0.f;
#pragma unroll
        for (int i = 0; i < 8; i++) {
            int e = lane + 32*i;
            float f = x[e];
            c += f * us[e];
            split2(f, g_Xh[(size_t)warp*DD + e], g_Xl[(size_t)warp*DD + e]);
        }
#pragma unroll
        for (int o = 16; o; o >>= 1) c += __shfl_xor_sync(0xffffffffu, c, o);
        if (lane == 0) g_c[warp] = c;
    } else {
        int idx = bx - 4608;
        int n0 = (idx & 31) * 64, d0 = ((idx >> 5) & 3) * 64, b = idx >> 7;
        const float* Xb = X + (size_t)b * NN * DD;
        for (int u = tid; u < 64*16; u += 256) {
            int r = u >> 4, c4 = u & 15;
            float4 v = *(const float4*)(Xb + (size_t)(n0 + r)*DD + d0 + c4*4);
            t[r][c4*4+0] = v.x; t[r][c4*4+1] = v.y; t[r][c4*4+2] = v.z; t[r][c4*4+3] = v.w;
        }
        __syncthreads();
        size_t ob = (size_t)b * DD * NN;
        for (int u = tid; u < 4096; u += 256) {
            int r = u >> 6, c = u & 63;
            g_Xth[ob + (size_t)(d0 + r)*NN + n0 + c] = __float2half_rn(t[c][r]);
        }
    }
}

// warp per row softmax (vectorized loads, FFMA exp; c already folded into S)
__global__ __launch_bounds__(256) void k_softmax() {
    int warp = (blockIdx.x * blockDim.x + threadIdx.x) >> 5;
    int lane = threadIdx.x & 31;
    const float* srow = g_S + (size_t)warp * NN;
    float4 v4[16];
    float mx = -1e30f;
#pragma unroll
    for (int i = 0; i < 16; i++) {
        float4 s = *(const float4*)(srow + i*128 + lane*4);
        v4[i] = s;
        mx = fmaxf(mx, fmaxf(fmaxf(s.x, s.y), fmaxf(s.z, s.w)));
    }
#pragma unroll
    for (int o = 16; o; o >>= 1) mx = fmaxf(mx, __shfl_xor_sync(0xffffffffu, mx, o));
    float sum = 0.f;
    size_t ro = (size_t)warp * NN;
#pragma unroll
    for (int i = 0; i < 16; i++) {
        float e0 = fexp(v4[i].x - mx), e1 = fexp(v4[i].y - mx);
        float e2 = fexp(v4[i].z - mx), e3 = fexp(v4[i].w - mx);
        h16 h0 = __float2half_rn(e0), h1 = __float2half_rn(e1);
        h16 h2 = __float2half_rn(e2), h3 = __float2half_rn(e3);
        sum += __half2float(h0) + __half2float(h1) + __half2float(h2) + __half2float(h3);
        __half2 p01 = __halves2half2(h0, h1), p23 = __halves2half2(h2, h3);
        uint2 pk;
        pk.x = *reinterpret_cast<uint32_t*>(&p01);
        pk.y = *reinterpret_cast<uint32_t*>(&p23);
        *(uint2*)(g_Ph + ro + i*128 + lane*4) = pk;
    }
#pragma unroll
    for (int o = 16; o; o >>= 1) sum += __shfl_xor_sync(0xffffffffu, sum, o);
    if (lane == 0) g_invl[warp] = 1.f / sum;
}

// ------------------------------------------------------------------ HMMA GEMM (32-K chunks, small 3-combo GEMMs)
#define TPAD   40
#define TILE_B (128*TPAD*2)       // 10240
#define OFF_AH 0
#define OFF_AL (1*TILE_B)
#define OFF_BH (2*TILE_B)
#define OFF_BL (3*TILE_B)
#define STAGE_B (4*TILE_B)        // 40960
#define GEMM_SMEM (2*STAGE_B)     // 81920

// EPI: 2 = bias+relu fp32   3 = fp16 hi-only
template<int EPI, int COMBOS>
__global__ __launch_bounds__(256, 2) void k_gemm(
    const h16* __restrict__ Ah, const h16* __restrict__ Al,
    const h16* __restrict__ Bh, const h16* __restrict__ Bl,
    float* __restrict__ Cf, h16* __restrict__ Ch, h16* __restrict__ Cl,
    const float* __restrict__ bias, const float* __restrict__ invl,
    int K, int ldc, int Mrows, size_t sA, size_t sB, size_t sC)
{
    extern __shared__ char smem[];
    uint32_t sb = smem_u32(smem);
    int tid = threadIdx.x;
    int lane = tid & 31, wid = tid >> 5;
    int g = lane >> 2, t = lane & 3;
    int warp_m = (wid & 1) * 64;
    int warp_n = (wid >> 1) * 32;
    int m0 = blockIdx.x * 128, n0 = blockIdx.y * 128, b = blockIdx.z;

    size_t go0 = (size_t)(tid >> 2) * K + (tid & 3) * 8;
    size_t go1 = go0 + (size_t)64 * K;
    uint32_t do0 = (uint32_t)((tid >> 2) * 80 + (tid & 3) * 16);
    uint32_t do1 = do0 + 64*80;

    int lr = ((lane >> 3) & 1) * 8 + (lane & 7);
    int lk = (lane >> 4) * 16;
    uint32_t a_off[4], b_off[2];
#pragma unroll
    for (int i = 0; i < 4; i++) a_off[i] = (uint32_t)((warp_m + i*16 + lr)*80 + lk);
#pragma unroll
    for (int p = 0; p < 2; p++) b_off[p] = (uint32_t)((warp_n + p*16 + lr)*80 + lk);

    const h16* pAh = Ah + (size_t)b*sA + (size_t)m0*K;
    const h16* pAl = (COMBOS >= 3) ? Al + (size_t)b*sA + (size_t)m0*K : nullptr;
    const h16* pBh = Bh + (size_t)b*sB + (size_t)n0*K;
    const h16* pBl = (COMBOS >= 2) ? Bl + (size_t)b*sB + (size_t)n0*K : nullptr;

    float acc[4][4][4];
#pragma unroll
    for (int i = 0; i < 4; i++)
#pragma unroll
        for (int j = 0; j < 4; j++)
#pragma unroll
            for (int r = 0; r < 4; r++) acc[i][j][r] = 0.f;

#define ISSUE_CHUNK(sbase, k0) do {                                          \
        CP16((sbase) + OFF_AH + do0, pAh + go0 + (k0));                      \
        CP16((sbase) + OFF_AH + do1, pAh + go1 + (k0));                      \
        if (COMBOS >= 3) {                                                   \
            CP16((sbase) + OFF_AL + do0, pAl + go0 + (k0));                  \
            CP16((sbase) + OFF_AL + do1, pAl + go1 + (k0));                  \
        }                                                                    \
        CP16((sbase) + OFF_BH + do0, pBh + go0 + (k0));                      \
        CP16((sbase) + OFF_BH + do1, pBh + go1 + (k0));                      \
        if (COMBOS >= 2) {                                                   \
            CP16((sbase) + OFF_BL + do0, pBl + go0 + (k0));                  \
            CP16((sbase) + OFF_BL + do1, pBl + go1 + (k0));                  \
        }                                                                    \
    } while (0)

    int nchunk = K >> 5;
    ISSUE_CHUNK(sb, 0);
    CP_COMMIT();

    for (int ch = 0; ch < nchunk; ch++) {
        int st = ch & 1;
        if (ch + 1 < nchunk) {
            ISSUE_CHUNK(sb + (uint32_t)(st ^ 1)*STAGE_B, (ch+1) << 5);
            CP_COMMIT();
            CP_WAIT(1);
        } else {
            CP_WAIT(0);
        }
        __syncthreads();

        uint32_t base = sb + (uint32_t)st * STAGE_B;
#pragma unroll
        for (int ks = 0; ks < 2; ks++) {
            uint32_t kb = ks * 32;
            uint32_t ah[4][4], al[4][4], bh[4][2], bl[4][2];
#pragma unroll
            for (int i = 0; i < 4; i++) {
                LDSM4(ah[i][0], ah[i][1], ah[i][2], ah[i][3], base + OFF_AH + a_off[i] + kb);
                if (COMBOS >= 3)
                    LDSM4(al[i][0], al[i][1], al[i][2], al[i][3], base + OFF_AL + a_off[i] + kb);
            }
#pragma unroll
            for (int p = 0; p < 2; p++) {
                LDSM4(bh[2*p][0], bh[2*p+1][0], bh[2*p][1], bh[2*p+1][1],
                      base + OFF_BH + b_off[p] + kb);
                if (COMBOS >= 2)
                    LDSM4(bl[2*p][0], bl[2*p+1][0], bl[2*p][1], bl[2*p+1][1],
                          base + OFF_BL + b_off[p] + kb);
            }
#pragma unroll
            for (int i = 0; i < 4; i++)
#pragma unroll
                for (int j = 0; j < 4; j++) {
                    MMA16816(acc[i][j], ah[i], bh[j]);
                    if (COMBOS >= 2) MMA16816(acc[i][j], ah[i], bl[j]);
                    if (COMBOS >= 3) MMA16816(acc[i][j], al[i], bh[j]);
                }
        }
        __syncthreads();
    }

#pragma unroll
    for (int i = 0; i < 4; i++) {
        int row0 = m0 + warp_m + i*16 + g;
#pragma unroll
        for (int j = 0; j < 4; j++) {
            int col = n0 + warp_n + j*8 + 2*t;
            if (EPI == 3) {
                size_t o0 = (size_t)b*sC + (size_t)row0*ldc + col;
                size_t o1 = o0 + 8*(size_t)ldc;
                *(__half2*)(Ch + o0) = __floats2half2_rn(acc[i][j][0], acc[i][j][1]);
                *(__half2*)(Ch + o1) = __floats2half2_rn(acc[i][j][2], acc[i][j][3]);
            } else {
                float b0 = bias[col], b1 = bias[col+1];
                float* d0 = Cf + (size_t)row0*ldc + col;
                float* d1 = d0 + 8*ldc;
                *(float2*)d0 = make_float2(fmaxf(acc[i][j][0]+b0, 0.f),
                                           fmaxf(acc[i][j][1]+b1, 0.f));
                *(float2*)d1 = make_float2(fmaxf(acc[i][j][2]+b0, 0.f),
                                           fmaxf(acc[i][j][3]+b1, 0.f));
            }
        }
    }
#undef ISSUE_CHUNK
}

// ------------------------------------------------------------------ HMMA GEMM, 64-K chunks, 1 barrier/chunk
// Row stride 144B. NSTAGE=2: issue-after-barrier. NSTAGE=3: issue-ahead-2 ring.
#define T64_B  (128*144)          // 18432 per tile

// EPI: 0 = fp32 + per-column batch-indexed bias (c fold)   1 = fp16 split + 1/l scale
// COMBOS: 2 = Ah.Bh + Ah.Bl   1 = Ah.Bh
template<int EPI, int COMBOS, int NSTAGE>
__global__ __launch_bounds__(256, 2) void k_gemm64(
    const h16* __restrict__ Ah,
    const h16* __restrict__ Bh, const h16* __restrict__ Bl,
    float* __restrict__ Cf, h16* __restrict__ Ch, h16* __restrict__ Cl,
    const float* __restrict__ bias, const float* __restrict__ invl,
    int K, int ldc, int Mrows, size_t sA, size_t sB, size_t sC)
{
    constexpr uint32_t OFF_A = 0;
    constexpr uint32_t OFF_B = T64_B;
    constexpr uint32_t OFF_B2 = 2*T64_B;
    constexpr uint32_t STAGE = (COMBOS >= 2 ? 3 : 2) * T64_B;

    extern __shared__ char smem[];
    uint32_t sb = smem_u32(smem);
    int tid = threadIdx.x;
    int lane = tid & 31, wid = tid >> 5;
    int g = lane >> 2, t = lane & 3;
    int warp_m = (wid & 1) * 64;
    int warp_n = (wid >> 1) * 32;
    int m0 = blockIdx.x * 128, n0 = blockIdx.y * 128, b = blockIdx.z;

    size_t gob = (size_t)(tid >> 3) * K + (tid & 7) * 8;
    uint32_t dob = (uint32_t)((tid >> 3) * 144 + (tid & 7) * 16);

    int lr = ((lane >> 3) & 1) * 8 + (lane & 7);
    int lk = (lane >> 4) * 16;
    uint32_t a_off[4], b_off[2];
#pragma unroll
    for (int i = 0; i < 4; i++) a_off[i] = (uint32_t)((warp_m + i*16 + lr)*144 + lk);
#pragma unroll
    for (int p = 0; p < 2; p++) b_off[p] = (uint32_t)((warp_n + p*16 + lr)*144 + lk);

    const h16* pAh = Ah + (size_t)b*sA + (size_t)m0*K;
    const h16* pBh = Bh + (size_t)b*sB + (size_t)n0*K;
    const h16* pBl = (COMBOS >= 2) ? Bl + (size_t)b*sB + (size_t)n0*K : nullptr;

    float sc0[4], sc1[4];
    if (EPI == 1 && invl) {
#pragma unroll
        for (int i = 0; i < 4; i++) {
            sc0[i] = invl[(size_t)b*Mrows + m0 + warp_m + i*16 + g];
            sc1[i] = invl[(size_t)b*Mrows + m0 + warp_m + i*16 + g + 8];
        }
    } else {
#pragma unroll
        for (int i = 0; i < 4; i++) { sc0[i] = 1.f; sc1[i] = 1.f; }
    }

    float acc[4][4][4];
#pragma unroll
    for (int i = 0; i < 4; i++)
#pragma unroll
        for (int j = 0; j < 4; j++)
#pragma unroll
            for (int r = 0; r < 4; r++) acc[i][j][r] = 0.f;

#define ISSUE64(sbase, k0) do {                                              \
        _Pragma("unroll")                                                    \
        for (int _i = 0; _i < 4; _i++) {                                     \
            size_t _g = gob + (size_t)(32*_i)*K + (k0);                      \
            uint32_t _d = dob + 32*_i*144;                                   \
            CP16((sbase) + OFF_A + _d, pAh + _g);                            \
            CP16((sbase) + OFF_B + _d, pBh + _g);                            \
            if (COMBOS >= 2) CP16((sbase) + OFF_B2 + _d, pBl + _g);          \
        }                                                                    \
    } while (0)

#define COMPUTE64(basev) do {                                                \
        _Pragma("unroll")                                                    \
        for (int ks = 0; ks < 4; ks++) {                                     \
            uint32_t kb = ks * 32;                                           \
            uint32_t ah[4][4], bh[4][2], bl[4][2];                           \
            _Pragma("unroll")                                                \
            for (int i = 0; i < 4; i++)                                      \
                LDSM4(ah[i][0], ah[i][1], ah[i][2], ah[i][3],                \
                      (basev) + OFF_A + a_off[i] + kb);                      \
            _Pragma("unroll")                                                \
            for (int p = 0; p < 2; p++) {                                    \
                LDSM4(bh[2*p][0], bh[2*p+1][0], bh[2*p][1], bh[2*p+1][1],    \
                      (basev) + OFF_B + b_off[p] + kb);                      \
                if (COMBOS >= 2)                                             \
                    LDSM4(bl[2*p][0], bl[2*p+1][0], bl[2*p][1], bl[2*p+1][1],\
                          (basev) + OFF_B2 + b_off[p] + kb);                 \
            }                                                                \
            _Pragma("unroll")                                                \
            for (int i = 0; i < 4; i++)                                      \
                _Pragma("unroll")                                            \
                for (int j = 0; j < 4; j++) {                                \
                    MMA16816(acc[i][j], ah[i], bh[j]);                       \
                    if (COMBOS >= 2) MMA16816(acc[i][j], ah[i], bl[j]);      \
                }                                                            \
        }                                                                    \
    } while (0)

    int nchunk = K >> 6;
    if (NSTAGE == 2) {
        ISSUE64(sb, 0);
        CP_COMMIT();
        for (int ch = 0; ch < nchunk; ch++) {
            CP_WAIT(0);
            __syncthreads();     // buffer (ch^1) consumed before this barrier
            uint32_t base = sb + (uint32_t)(ch & 1) * STAGE;
            if (ch + 1 < nchunk) {
                ISSUE64(sb + (uint32_t)((ch + 1) & 1) * STAGE, (ch+1) << 6);
                CP_COMMIT();
            }
            COMPUTE64(base);
        }
    } else {
        ISSUE64(sb, 0);
        CP_COMMIT();
        if (nchunk > 1) ISSUE64(sb + STAGE, 64);
        CP_COMMIT();
        int st = 0;
        for (int ch = 0; ch < nchunk; ch++) {
            CP_WAIT(1);
            __syncthreads();     // ring slot (st+2)%3 consumed before this barrier
            uint32_t base = sb + (uint32_t)st * STAGE;
            int st2 = st + 2; if (st2 >= 3) st2 -= 3;
            if (ch + 2 < nchunk) ISSUE64(sb + (uint32_t)st2 * STAGE, (ch+2) << 6);
            CP_COMMIT();
            COMPUTE64(base);
            st++; if (st == 3) st = 0;
        }
    }

    // ---- epilogue ----
#pragma unroll
    for (int i = 0; i < 4; i++) {
        int row0 = m0 + warp_m + i*16 + g;
#pragma unroll
        for (int j = 0; j < 4; j++) {
            int col = n0 + warp_n + j*8 + 2*t;
            if (EPI == 0) {
                float c0 = bias[(size_t)b*ldc + col], c1 = bias[(size_t)b*ldc + col + 1];
                float* d0 = Cf + (size_t)b*sC + (size_t)row0*ldc + col;
                float* d1 = d0 + 8*ldc;
                *(float2*)d0 = make_float2(acc[i][j][0] + c0, acc[i][j][1] + c1);
                *(float2*)d1 = make_float2(acc[i][j][2] + c0, acc[i][j][3] + c1);
            } else {
                float v0 = acc[i][j][0]*sc0[i], v1 = acc[i][j][1]*sc0[i];
                float v2 = acc[i][j][2]*sc1[i], v3 = acc[i][j][3]*sc1[i];
                h16 h0, l0, h1, l1, h2, l2, h3, l3;
                split2(v0, h0, l0); split2(v1, h1, l1);
                split2(v2, h2, l2); split2(v3, h3, l3);
                size_t o0 = (size_t)b*sC + (size_t)row0*ldc + col;
                size_t o1 = o0 + 8*(size_t)ldc;
                *(__half2*)(Ch + o0) = __halves2half2(h0, h1);
                *(__half2*)(Ch + o1) = __halves2half2(h2, h3);
                *(__half2*)(Cl + o0) = __halves2half2(l0, l1);
                *(__half2*)(Cl + o1) = __halves2half2(l2, l3);
            }
        }
    }
#undef ISSUE64
#undef COMPUTE64
}

#define S_SMEM   (2*3*T64_B)   // 110592 (2 stages x 3 tiles)
#define PV_SMEM  (3*2*T64_B)   // 110592 (3 stages x 2 tiles)

// ------------------------------------------------------------------ launch
extern "C" void kernel_launch(void* const* d_in, const int* in_sizes, int n_in,
                              void* d_out, int out_size) {
    const float* inp = (const float*)d_in[0];
    const float* Wq  = (const float*)d_in[1];
    const float* bq  = (const float*)d_in[2];
    const float* Wk  = (const float*)d_in[3];
    // bk (d_in[4]) provably drops out of the softmax — unused.
    const float* Wo  = (const float*)d_in[5];
    const float* bo  = (const float*)d_in[6];
    float* out = (float*)d_out;

    float *pS, *pInvl, *pCvec;
    h16 *pXh, *pXl, *pXth, *pAph, *pPh, *pAggh, *pAggl;
    h16 *pWth, *pWtl, *pWoth, *pWotl;
    cudaGetSymbolAddress((void**)&pS, g_S);
    cudaGetSymbolAddress((void**)&pInvl, g_invl);
    cudaGetSymbolAddress((void**)&pCvec, g_c);
    cudaGetSymbolAddress((void**)&pXh, g_Xh);   cudaGetSymbolAddress((void**)&pXl, g_Xl);
    cudaGetSymbolAddress((void**)&pXth, g_Xth);
    cudaGetSymbolAddress((void**)&pAph, g_Aph);
    cudaGetSymbolAddress((void**)&pPh, g_Ph);
    cudaGetSymbolAddress((void**)&pAggh, g_aggh); cudaGetSymbolAddress((void**)&pAggl, g_aggl);
    cudaGetSymbolAddress((void**)&pWth, g_Wth); cudaGetSymbolAddress((void**)&pWtl, g_Wtl);
    cudaGetSymbolAddress((void**)&pWoth, g_Woth); cudaGetSymbolAddress((void**)&pWotl, g_Wotl);

    cudaFuncSetAttribute((const void*)k_gemm<3,3>,     cudaFuncAttributeMaxDynamicSharedMemorySize, GEMM_SMEM);
    cudaFuncSetAttribute((const void*)k_gemm<2,3>,     cudaFuncAttributeMaxDynamicSharedMemorySize, GEMM_SMEM);
    cudaFuncSetAttribute((const void*)k_gemm64<0,2,2>, cudaFuncAttributeMaxDynamicSharedMemorySize, S_SMEM);
    cudaFuncSetAttribute((const void*)k_gemm64<1,1,3>, cudaFuncAttributeMaxDynamicSharedMemorySize, PV_SMEM);

    // 1) W = Wq Wk^T, u = Wk bq
    k_precomp<<<DD + 1, DD>>>(Wq, Wk, bq);
    // 2) all splits/transposes + c
    k_prep<<<6656, 256>>>(inp, Wo);
    // 3) A' = X @ W -> fp16 (hi only; 3 combos for accuracy)
    k_gemm<3,3><<<dim3(ROWS/128, 2, 1), 256, GEMM_SMEM>>>(
        pXh, pXl, pWth, pWtl, nullptr, pAph, nullptr, nullptr, nullptr,
        DD, DD, ROWS, 0, 0, 0);
    // 4) S = A' @ X^T + c  (2 combos, 64-K chunks, 1 barrier/chunk) -> fp32  [profiled]
    k_gemm64<0,2,2><<<dim3(NN/128, NN/128, BB), 256, S_SMEM>>>(
        pAph, pXh, pXl, pS, nullptr, nullptr, pCvec, nullptr,
        DD, NN, NN, (size_t)NN*DD, (size_t)NN*DD, (size_t)NN*NN);
    // 5) softmax -> Ph + 1/l  (FFMA exp)
    k_softmax<<<ROWS/8, 256>>>();
    // 6) agg = (Ph @ Xth) / l  (K=2048, 1 combo, 3-stage ring) -> fp16 splits
    k_gemm64<1,1,3><<<dim3(NN/128, 2, BB), 256, PV_SMEM>>>(
        pPh, pXth, nullptr, nullptr, pAggh, pAggl, nullptr, pInvl,
        NN, DD, NN, (size_t)NN*NN, (size_t)DD*NN, (size_t)NN*DD);
    // 7) out = relu(agg @ Wo + bo) -> fp32  (3 combos)
    k_gemm<2,3><<<dim3(ROWS/128, 2, 1), 256, GEMM_SMEM>>>(
        pAggh, pAggl, pWoth, pWotl, out, nullptr, nullptr, bo, nullptr,
        DD, DD, ROWS, 0, 0, 0);
}

// round 13
// speedup vs baseline: 1.3637x; 1.0003x over previous
#include <cuda_runtime.h>
#include <cuda_fp16.h>
#include <cstdint>

#define DD 256
#define BB 16
#define NN 2048
#define ROWS (BB*NN)

typedef __half h16;

// ------------------------------------------------------------------ scratch
__device__ float g_W[DD*DD];                 // Wq @ Wk^T
__device__ float g_u[DD];                    // Wk @ bq
__device__ float g_c[ROWS];                  // X . u  (per key row)
__device__ float g_mt[(size_t)ROWS*16];      // per (row, ntile) max
__device__ float g_st[(size_t)ROWS*16];      // per (row, ntile) sum
__device__ float g_cf[(size_t)ROWS*16];      // per (row, ntile) exp(mt-m)/l

__device__ h16 g_Xh[(size_t)ROWS*DD],  g_Xl[(size_t)ROWS*DD];    // X splits (row-major)
__device__ h16 g_Xth[(size_t)BB*DD*NN];                          // X^T (hi only)
__device__ h16 g_Aph[(size_t)ROWS*DD];                           // A' = X@W (fp16)
__device__ h16 g_Pt[(size_t)ROWS*NN];                            // exp(s - m_tile) fp16
__device__ h16 g_aggh[(size_t)ROWS*DD], g_aggl[(size_t)ROWS*DD]; // agg splits
__device__ h16 g_Wth[DD*DD], g_Wtl[DD*DD];   // (WqWk^T)^T splits
__device__ h16 g_Woth[DD*DD], g_Wotl[DD*DD]; // Wo^T splits

// ------------------------------------------------------------------ helpers
__device__ __forceinline__ uint32_t smem_u32(const void* p) {
    uint32_t a;
    asm("{ .reg .u64 t; cvta.to.shared.u64 t, %1; cvt.u32.u64 %0, t; }" : "=r"(a) : "l"(p));
    return a;
}
#define CP16(dst, src) \
    asm volatile("cp.async.cg.shared.global [%0], [%1], 16;" :: "r"(dst), "l"(src))
#define CP_COMMIT() asm volatile("cp.async.commit_group;" ::: "memory")
#define CP_WAIT(n)  asm volatile("cp.async.wait_group %0;" :: "n"(n) : "memory")

#define MMA16816(c, a, b)                                                     \
    asm volatile("mma.sync.aligned.m16n8k16.row.col.f32.f16.f16.f32 "         \
        "{%0,%1,%2,%3},{%4,%5,%6,%7},{%8,%9},{%0,%1,%2,%3};"                  \
        : "+f"((c)[0]), "+f"((c)[1]), "+f"((c)[2]), "+f"((c)[3])              \
        : "r"((a)[0]), "r"((a)[1]), "r"((a)[2]), "r"((a)[3]),                 \
          "r"((b)[0]), "r"((b)[1]))

#define LDSM4(r0, r1, r2, r3, addr)                                           \
    asm volatile("ldmatrix.sync.aligned.m8n8.x4.shared.b16 {%0,%1,%2,%3}, [%4];" \
        : "=r"(r0), "=r"(r1), "=r"(r2), "=r"(r3) : "r"(addr))

__device__ __forceinline__ void split2(float f, h16& h, h16& l) {
    h = __float2half_rn(f);
    l = __float2half_rn(f - __half2float(h));
}

// FFMA-pipe exp for y <= 0: 2^(y*log2e), degree-6 poly; rel err ~1.6e-5.
__device__ __forceinline__ float fexp(float y) {
    float t = y * 1.4426950408889634f;
    int i = __float2int_rd(t);
    float f = t - (float)i;
    float p = 1.5403530e-4f;
    p = fmaf(p, f, 1.3333558e-3f);
    p = fmaf(p, f, 9.6181291e-3f);
    p = fmaf(p, f, 5.5504109e-2f);
    p = fmaf(p, f, 2.4022651e-1f);
    p = fmaf(p, f, 6.9314718e-1f);
    p = fmaf(p, f, 1.0f);
    i = (i < -126) ? -126 : i;
    return p * __int_as_float((uint32_t)(i + 127) << 23);
}

// ------------------------------------------------------------------ precompute: W = Wq@Wk^T, u = Wk@bq
__global__ void k_precomp(const float* __restrict__ Wq, const float* __restrict__ Wk,
                          const float* __restrict__ bq) {
    __shared__ float v[DD];
    int bx = blockIdx.x;
    if (bx < DD) {
        v[threadIdx.x] = Wq[bx*DD + threadIdx.x];
        __syncthreads();
        int j = threadIdx.x;
        const float* wk = Wk + j*DD;
        float s = 0.f;
#pragma unroll 8
        for (int e = 0; e < DD; e++) s += v[e] * wk[e];
        g_W[bx*DD + j] = s;
    } else {
        v[threadIdx.x] = bq[threadIdx.x];
        __syncthreads();
        int i = threadIdx.x;
        const float* wk = Wk + i*DD;
        float s = 0.f;
#pragma unroll 8
        for (int e = 0; e < DD; e++) s += wk[e] * v[e];
        g_u[i] = s;
    }
}

// ------------------------------------------------------------------ fused prep
__global__ __launch_bounds__(256) void k_prep(const float* __restrict__ X,
                                              const float* __restrict__ Wo) {
    __shared__ float t[64][65];
    __shared__ float us[DD];
    int bx = blockIdx.x, tid = threadIdx.x;
    if (bx < 512) {
        int which = bx >> 8, j = bx & 255, d = tid;
        const float* src = which ? Wo : g_W;
        h16* dh = which ? g_Woth : g_Wth;
        h16* dl = which ? g_Wotl : g_Wtl;
        float f = src[d*DD + j];
        split2(f, dh[j*DD + d], dl[j*DD + d]);
    } else if (bx < 4608) {
        if (tid < DD) us[tid] = g_u[tid];
        __syncthreads();
        int warp = (bx - 512)*8 + (tid >> 5);
        int lane = tid & 31;
        const float* x = X + (size_t)warp * DD;
        float c = 0.f;
#pragma unroll
        for (int i = 0; i < 8; i++) {
            int e = lane + 32*i;
            float f = x[e];
            c += f * us[e];
            split2(f, g_Xh[(size_t)warp*DD + e], g_Xl[(size_t)warp*DD + e]);
        }
#pragma unroll
        for (int o = 16; o; o >>= 1) c += __shfl_xor_sync(0xffffffffu, c, o);
        if (lane == 0) g_c[warp] = c;
    } else {
        int idx = bx - 4608;
        int n0 = (idx & 31) * 64, d0 = ((idx >> 5) & 3) * 64, b = idx >> 7;
        const float* Xb = X + (size_t)b * NN * DD;
        for (int u = tid; u < 64*16; u += 256) {
            int r = u >> 4, c4 = u & 15;
            float4 v = *(const float4*)(Xb + (size_t)(n0 + r)*DD + d0 + c4*4);
            t[r][c4*4+0] = v.x; t[r][c4*4+1] = v.y; t[r][c4*4+2] = v.z; t[r][c4*4+3] = v.w;
        }
        __syncthreads();
        size_t ob = (size_t)b * DD * NN;
        for (int u = tid; u < 4096; u += 256) {
            int r = u >> 6, c = u & 63;
            g_Xth[ob + (size_t)(d0 + r)*NN + n0 + c] = __float2half_rn(t[c][r]);
        }
    }
}

// per-row normalization: m = max mt, l = sum st*exp(mt-m), cf = exp(mt-m)/l
__global__ __launch_bounds__(256) void k_norm() {
    int r = blockIdx.x * 256 + threadIdx.x;
    float mt[16], m = -1e30f;
#pragma unroll
    for (int q = 0; q < 16; q++) {
        mt[q] = g_mt[(size_t)r*16 + q];
        m = fmaxf(m, mt[q]);
    }
    float e[16], l = 0.f;
#pragma unroll
    for (int q = 0; q < 16; q++) {
        e[q] = fexp(mt[q] - m);
        l += g_st[(size_t)r*16 + q] * e[q];
    }
    float inv = 1.f / l;
#pragma unroll
    for (int q = 0; q < 16; q++)
        g_cf[(size_t)r*16 + q] = e[q] * inv;
}

// ------------------------------------------------------------------ HMMA GEMM (32-K chunks, small 3-combo GEMMs)
#define TPAD   40
#define TILE_B (128*TPAD*2)       // 10240
#define OFF_AH 0
#define OFF_AL (1*TILE_B)
#define OFF_BH (2*TILE_B)
#define OFF_BL (3*TILE_B)
#define STAGE_B (4*TILE_B)        // 40960
#define GEMM_SMEM (2*STAGE_B)     // 81920

// EPI: 2 = bias+relu fp32   3 = fp16 hi-only
template<int EPI, int COMBOS>
__global__ __launch_bounds__(256, 2) void k_gemm(
    const h16* __restrict__ Ah, const h16* __restrict__ Al,
    const h16* __restrict__ Bh, const h16* __restrict__ Bl,
    float* __restrict__ Cf, h16* __restrict__ Ch,
    const float* __restrict__ bias,
    int K, int ldc, size_t sC)
{
    extern __shared__ char smem[];
    uint32_t sb = smem_u32(smem);
    int tid = threadIdx.x;
    int lane = tid & 31, wid = tid >> 5;
    int g = lane >> 2, t = lane & 3;
    int warp_m = (wid & 1) * 64;
    int warp_n = (wid >> 1) * 32;
    int m0 = blockIdx.x * 128, n0 = blockIdx.y * 128, b = blockIdx.z;

    size_t go0 = (size_t)(tid >> 2) * K + (tid & 3) * 8;
    size_t go1 = go0 + (size_t)64 * K;
    uint32_t do0 = (uint32_t)((tid >> 2) * 80 + (tid & 3) * 16);
    uint32_t do1 = do0 + 64*80;

    int lr = ((lane >> 3) & 1) * 8 + (lane & 7);
    int lk = (lane >> 4) * 16;
    uint32_t a_off[4], b_off[2];
#pragma unroll
    for (int i = 0; i < 4; i++) a_off[i] = (uint32_t)((warp_m + i*16 + lr)*80 + lk);
#pragma unroll
    for (int p = 0; p < 2; p++) b_off[p] = (uint32_t)((warp_n + p*16 + lr)*80 + lk);

    const h16* pAh = Ah + (size_t)m0*K;
    const h16* pAl = (COMBOS >= 3) ? Al + (size_t)m0*K : nullptr;
    const h16* pBh = Bh + (size_t)n0*K;
    const h16* pBl = (COMBOS >= 2) ? Bl + (size_t)n0*K : nullptr;

    float acc[4][4][4];
#pragma unroll
    for (int i = 0; i < 4; i++)
#pragma unroll
        for (int j = 0; j < 4; j++)
#pragma unroll
            for (int r = 0; r < 4; r++) acc[i][j][r] = 0.f;

#define ISSUE_CHUNK(sbase, k0) do {                                          \
        CP16((sbase) + OFF_AH + do0, pAh + go0 + (k0));                      \
        CP16((sbase) + OFF_AH + do1, pAh + go1 + (k0));                      \
        if (COMBOS >= 3) {                                                   \
            CP16((sbase) + OFF_AL + do0, pAl + go0 + (k0));                  \
            CP16((sbase) + OFF_AL + do1, pAl + go1 + (k0));                  \
        }                                                                    \
        CP16((sbase) + OFF_BH + do0, pBh + go0 + (k0));                      \
        CP16((sbase) + OFF_BH + do1, pBh + go1 + (k0));                      \
        if (COMBOS >= 2) {                                                   \
            CP16((sbase) + OFF_BL + do0, pBl + go0 + (k0));                  \
            CP16((sbase) + OFF_BL + do1, pBl + go1 + (k0));                  \
        }                                                                    \
    } while (0)

    int nchunk = K >> 5;
    ISSUE_CHUNK(sb, 0);
    CP_COMMIT();

    for (int ch = 0; ch < nchunk; ch++) {
        int st = ch & 1;
        if (ch + 1 < nchunk) {
            ISSUE_CHUNK(sb + (uint32_t)(st ^ 1)*STAGE_B, (ch+1) << 5);
            CP_COMMIT();
            CP_WAIT(1);
        } else {
            CP_WAIT(0);
        }
        __syncthreads();

        uint32_t base = sb + (uint32_t)st * STAGE_B;
#pragma unroll
        for (int ks = 0; ks < 2; ks++) {
            uint32_t kb = ks * 32;
            uint32_t ah[4][4], al[4][4], bh[4][2], bl[4][2];
#pragma unroll
            for (int i = 0; i < 4; i++) {
                LDSM4(ah[i][0], ah[i][1], ah[i][2], ah[i][3], base + OFF_AH + a_off[i] + kb);
                if (COMBOS >= 3)
                    LDSM4(al[i][0], al[i][1], al[i][2], al[i][3], base + OFF_AL + a_off[i] + kb);
            }
#pragma unroll
            for (int p = 0; p < 2; p++) {
                LDSM4(bh[2*p][0], bh[2*p+1][0], bh[2*p][1], bh[2*p+1][1],
                      base + OFF_BH + b_off[p] + kb);
                if (COMBOS >= 2)
                    LDSM4(bl[2*p][0], bl[2*p+1][0], bl[2*p][1], bl[2*p+1][1],
                          base + OFF_BL + b_off[p] + kb);
            }
#pragma unroll
            for (int i = 0; i < 4; i++)
#pragma unroll
                for (int j = 0; j < 4; j++) {
                    MMA16816(acc[i][j], ah[i], bh[j]);
                    if (COMBOS >= 2) MMA16816(acc[i][j], ah[i], bl[j]);
                    if (COMBOS >= 3) MMA16816(acc[i][j], al[i], bh[j]);
                }
        }
        __syncthreads();
    }

#pragma unroll
    for (int i = 0; i < 4; i++) {
        int row0 = m0 + warp_m + i*16 + g;
#pragma unroll
        for (int j = 0; j < 4; j++) {
            int col = n0 + warp_n + j*8 + 2*t;
            if (EPI == 3) {
                size_t o0 = (size_t)row0*ldc + col;
                size_t o1 = o0 + 8*(size_t)ldc;
                *(__half2*)(Ch + o0) = __floats2half2_rn(acc[i][j][0], acc[i][j][1]);
                *(__half2*)(Ch + o1) = __floats2half2_rn(acc[i][j][2], acc[i][j][3]);
            } else {
                float b0 = bias[col], b1 = bias[col+1];
                float* d0 = Cf + (size_t)row0*ldc + col;
                float* d1 = d0 + 8*ldc;
                *(float2*)d0 = make_float2(fmaxf(acc[i][j][0]+b0, 0.f),
                                           fmaxf(acc[i][j][1]+b1, 0.f));
                *(float2*)d1 = make_float2(fmaxf(acc[i][j][2]+b0, 0.f),
                                           fmaxf(acc[i][j][3]+b1, 0.f));
            }
        }
    }
#undef ISSUE_CHUNK
}

// ------------------------------------------------------------------ HMMA GEMM, 64-K chunks, 1 barrier/chunk
// EPI: 1 = fp16 hi/lo split   4 = exp-tile (fused softmax pieces)
// SCA: scale A fragments by per-(row, ktile) Cfac (PV normalization).
#define T64_B  (128*144)

template<int EPI, int COMBOS, int NSTAGE, bool SCA>
__global__ __launch_bounds__(256, 2) void k_gemm64(
    const h16* __restrict__ Ah,
    const h16* __restrict__ Bh, const h16* __restrict__ Bl,
    h16* __restrict__ Ch, h16* __restrict__ Cl,
    const float* __restrict__ bias, const float* __restrict__ Cfac,
    float* __restrict__ Mt, float* __restrict__ St,
    int K, int ldc, size_t sA, size_t sB, size_t sC)
{
    constexpr uint32_t OFF_A = 0;
    constexpr uint32_t OFF_B = T64_B;
    constexpr uint32_t OFF_B2 = 2*T64_B;
    constexpr uint32_t STAGE = (COMBOS >= 2 ? 3 : 2) * T64_B;

    extern __shared__ char smem[];
    uint32_t sb = smem_u32(smem);
    int tid = threadIdx.x;
    int lane = tid & 31, wid = tid >> 5;
    int g = lane >> 2, t = lane & 3;
    int warp_m = (wid & 1) * 64;
    int warp_n = (wid >> 1) * 32;
    int m0 = blockIdx.x * 128, n0 = blockIdx.y * 128, b = blockIdx.z;

    size_t gob = (size_t)(tid >> 3) * K + (tid & 7) * 8;
    uint32_t dob = (uint32_t)((tid >> 3) * 144 + (tid & 7) * 16);

    int lr = ((lane >> 3) & 1) * 8 + (lane & 7);
    int lk = (lane >> 4) * 16;
    uint32_t a_off[4], b_off[2];
#pragma unroll
    for (int i = 0; i < 4; i++) a_off[i] = (uint32_t)((warp_m + i*16 + lr)*144 + lk);
#pragma unroll
    for (int p = 0; p < 2; p++) b_off[p] = (uint32_t)((warp_n + p*16 + lr)*144 + lk);

    const h16* pAh = Ah + (size_t)b*sA + (size_t)m0*K;
    const h16* pBh = Bh + (size_t)b*sB + (size_t)n0*K;
    const h16* pBl = (COMBOS >= 2) ? Bl + (size_t)b*sB + (size_t)n0*K : nullptr;

    float acc[4][4][4];
#pragma unroll
    for (int i = 0; i < 4; i++)
#pragma unroll
        for (int j = 0; j < 4; j++)
#pragma unroll
            for (int r = 0; r < 4; r++) acc[i][j][r] = 0.f;

    __half2 hA[4], hB[4];

#define ISSUE64(sbase, k0) do {                                              \
        _Pragma("unroll")                                                    \
        for (int _i = 0; _i < 4; _i++) {                                     \
            size_t _g = gob + (size_t)(32*_i)*K + (k0);                      \
            uint32_t _d = dob + 32*_i*144;                                   \
            CP16((sbase) + OFF_A + _d, pAh + _g);                            \
            CP16((sbase) + OFF_B + _d, pBh + _g);                            \
            if (COMBOS >= 2) CP16((sbase) + OFF_B2 + _d, pBl + _g);          \
        }                                                                    \
    } while (0)

#define COMPUTE64(basev) do {                                                \
        _Pragma("unroll")                                                    \
        for (int ks = 0; ks < 4; ks++) {                                     \
            uint32_t kb = ks * 32;                                           \
            uint32_t ah[4][4], bh[4][2], bl[4][2];                           \
            _Pragma("unroll")                                                \
            for (int i = 0; i < 4; i++) {                                    \
                LDSM4(ah[i][0], ah[i][1], ah[i][2], ah[i][3],                \
                      (basev) + OFF_A + a_off[i] + kb);                      \
                if (SCA) {                                                   \
                    *(__half2*)&ah[i][0] = __hmul2(*(__half2*)&ah[i][0], hA[i]); \
                    *(__half2*)&ah[i][1] = __hmul2(*(__half2*)&ah[i][1], hB[i]); \
                    *(__half2*)&ah[i][2] = __hmul2(*(__half2*)&ah[i][2], hA[i]); \
                    *(__half2*)&ah[i][3] = __hmul2(*(__half2*)&ah[i][3], hB[i]); \
                }                                                            \
            }                                                                \
            _Pragma("unroll")                                                \
            for (int p = 0; p < 2; p++) {                                    \
                LDSM4(bh[2*p][0], bh[2*p+1][0], bh[2*p][1], bh[2*p+1][1],    \
                      (basev) + OFF_B + b_off[p] + kb);                      \
                if (COMBOS >= 2)                                             \
                    LDSM4(bl[2*p][0], bl[2*p+1][0], bl[2*p][1], bl[2*p+1][1],\
                          (basev) + OFF_B2 + b_off[p] + kb);                 \
            }                                                                \
            _Pragma("unroll")                                                \
            for (int i = 0; i < 4; i++)                                      \
                _Pragma("unroll")                                            \
                for (int j = 0; j < 4; j++) {                                \
                    MMA16816(acc[i][j], ah[i], bh[j]);                       \
                    if (COMBOS >= 2) MMA16816(acc[i][j], ah[i], bl[j]);      \
                }                                                            \
        }                                                                    \
    } while (0)

#define LOAD_CF(ch) do {                                                     \
        if (SCA && ((ch) & 1) == 0) {                                        \
            int kt = (ch) >> 1;                                              \
            _Pragma("unroll")                                                \
            for (int i = 0; i < 4; i++) {                                    \
                float fA = Cfac[((size_t)b*NN + m0 + warp_m + i*16 + g)*16 + kt];     \
                float fB = Cfac[((size_t)b*NN + m0 + warp_m + i*16 + g + 8)*16 + kt]; \
                hA[i] = __half2half2(__float2half_rn(fA));                   \
                hB[i] = __half2half2(__float2half_rn(fB));                   \
            }                                                                \
        }                                                                    \
    } while (0)

    int nchunk = K >> 6;
    if (NSTAGE == 2) {
        ISSUE64(sb, 0);
        CP_COMMIT();
        for (int ch = 0; ch < nchunk; ch++) {
            CP_WAIT(0);
            __syncthreads();
            uint32_t base = sb + (uint32_t)(ch & 1) * STAGE;
            if (ch + 1 < nchunk) {
                ISSUE64(sb + (uint32_t)((ch + 1) & 1) * STAGE, (ch+1) << 6);
                CP_COMMIT();
            }
            LOAD_CF(ch);
            COMPUTE64(base);
        }
    } else {
        ISSUE64(sb, 0);
        CP_COMMIT();
        if (nchunk > 1) ISSUE64(sb + STAGE, 64);
        CP_COMMIT();
        int st = 0;
        for (int ch = 0; ch < nchunk; ch++) {
            CP_WAIT(1);
            __syncthreads();
            uint32_t base = sb + (uint32_t)st * STAGE;
            int st2 = st + 2; if (st2 >= 3) st2 -= 3;
            if (ch + 2 < nchunk) ISSUE64(sb + (uint32_t)st2 * STAGE, (ch+2) << 6);
            CP_COMMIT();
            LOAD_CF(ch);
            COMPUTE64(base);
            st++; if (st == 3) st = 0;
        }
    }

    // ---- epilogue ----
    if (EPI == 4) {
        // fused: c-add, per-tile row max, exp, fp16 store, row sums, mt/st out
        __syncthreads();                  // mainloop smem done; reuse for reductions
        float* red   = (float*)smem;      // [128][4]
        float* bcast = red + 512;         // [128]
        float* sred  = bcast + 128;       // [128][4]
        int ntile = blockIdx.y;

        float mA[4], mB[4];
#pragma unroll
        for (int i = 0; i < 4; i++) {
            mA[i] = -1e30f; mB[i] = -1e30f;
#pragma unroll
            for (int j = 0; j < 4; j++) {
                int col = n0 + warp_n + j*8 + 2*t;
                float c0 = bias[(size_t)b*ldc + col], c1 = bias[(size_t)b*ldc + col + 1];
                acc[i][j][0] += c0; acc[i][j][1] += c1;
                acc[i][j][2] += c0; acc[i][j][3] += c1;
                mA[i] = fmaxf(mA[i], fmaxf(acc[i][j][0], acc[i][j][1]));
                mB[i] = fmaxf(mB[i], fmaxf(acc[i][j][2], acc[i][j][3]));
            }
            mA[i] = fmaxf(mA[i], __shfl_xor_sync(0xffffffffu, mA[i], 1));
            mA[i] = fmaxf(mA[i], __shfl_xor_sync(0xffffffffu, mA[i], 2));
            mB[i] = fmaxf(mB[i], __shfl_xor_sync(0xffffffffu, mB[i], 1));
            mB[i] = fmaxf(mB[i], __shfl_xor_sync(0xffffffffu, mB[i], 2));
        }
        if (t == 0) {
#pragma unroll
            for (int i = 0; i < 4; i++) {
                red[(warp_m + i*16 + g)*4 + (wid >> 1)]     = mA[i];
                red[(warp_m + i*16 + g + 8)*4 + (wid >> 1)] = mB[i];
            }
        }
        __syncthreads();
        if (tid < 128)
            bcast[tid] = fmaxf(fmaxf(red[tid*4], red[tid*4+1]),
                               fmaxf(red[tid*4+2], red[tid*4+3]));
        __syncthreads();
#pragma unroll
        for (int i = 0; i < 4; i++) {
            int rA = warp_m + i*16 + g, rB = rA + 8;
            float emA = bcast[rA], emB = bcast[rB];
            float sA = 0.f, sB = 0.f;
            size_t oA = ((size_t)b*sC >> 0) + (size_t)(m0 + rA)*ldc + n0;
            size_t oB = oA + 8*(size_t)ldc;
#pragma unroll
            for (int j = 0; j < 4; j++) {
                int cl = warp_n + j*8 + 2*t;
                float p0 = fexp(acc[i][j][0] - emA), p1 = fexp(acc[i][j][1] - emA);
                float p2 = fexp(acc[i][j][2] - emB), p3 = fexp(acc[i][j][3] - emB);
                __half2 q01 = __floats2half2_rn(p0, p1);
                __half2 q23 = __floats2half2_rn(p2, p3);
                sA += __low2float(q01) + __high2float(q01);
                sB += __low2float(q23) + __high2float(q23);
                *(__half2*)(Ch + oA + cl) = q01;
                *(__half2*)(Ch + oB + cl) = q23;
            }
            sA += __shfl_xor_sync(0xffffffffu, sA, 1);
            sA += __shfl_xor_sync(0xffffffffu, sA, 2);
            sB += __shfl_xor_sync(0xffffffffu, sB, 1);
            sB += __shfl_xor_sync(0xffffffffu, sB, 2);
            if (t == 0) {
                sred[rA*4 + (wid >> 1)] = sA;
                sred[rB*4 + (wid >> 1)] = sB;
            }
        }
        __syncthreads();
        if (tid < 128) {
            size_t o = ((size_t)b*NN + m0 + tid)*16 + ntile;
            Mt[o] = bcast[tid];
            St[o] = sred[tid*4] + sred[tid*4+1] + sred[tid*4+2] + sred[tid*4+3];
        }
    } else {
#pragma unroll
        for (int i = 0; i < 4; i++) {
            int row0 = m0 + warp_m + i*16 + g;
#pragma unroll
            for (int j = 0; j < 4; j++) {
                int col = n0 + warp_n + j*8 + 2*t;
                float v0 = acc[i][j][0], v1 = acc[i][j][1];
                float v2 = acc[i][j][2], v3 = acc[i][j][3];
                h16 h0, l0, h1, l1, h2, l2, h3, l3;
                split2(v0, h0, l0); split2(v1, h1, l1);
                split2(v2, h2, l2); split2(v3, h3, l3);
                size_t o0 = (size_t)b*sC + (size_t)row0*ldc + col;
                size_t o1 = o0 + 8*(size_t)ldc;
                *(__half2*)(Ch + o0) = __halves2half2(h0, h1);
                *(__half2*)(Ch + o1) = __halves2half2(h2, h3);
                *(__half2*)(Cl + o0) = __halves2half2(l0, l1);
                *(__half2*)(Cl + o1) = __halves2half2(l2, l3);
            }
        }
    }
#undef ISSUE64
#undef COMPUTE64
#undef LOAD_CF
}

#define S_SMEM   (2*3*T64_B)   // 110592 (2 stages x 3 tiles)
#define PV_SMEM  (3*2*T64_B)   // 110592 (3 stages x 2 tiles)

// ------------------------------------------------------------------ launch
extern "C" void kernel_launch(void* const* d_in, const int* in_sizes, int n_in,
                              void* d_out, int out_size) {
    const float* inp = (const float*)d_in[0];
    const float* Wq  = (const float*)d_in[1];
    const float* bq  = (const float*)d_in[2];
    const float* Wk  = (const float*)d_in[3];
    // bk (d_in[4]) provably drops out of the softmax — unused.
    const float* Wo  = (const float*)d_in[5];
    const float* bo  = (const float*)d_in[6];
    float* out = (float*)d_out;

    float *pCvec, *pMt, *pSt, *pCf;
    h16 *pXh, *pXl, *pXth, *pAph, *pPt, *pAggh, *pAggl;
    h16 *pWth, *pWtl, *pWoth, *pWotl;
    cudaGetSymbolAddress((void**)&pCvec, g_c);
    cudaGetSymbolAddress((void**)&pMt, g_mt);
    cudaGetSymbolAddress((void**)&pSt, g_st);
    cudaGetSymbolAddress((void**)&pCf, g_cf);
    cudaGetSymbolAddress((void**)&pXh, g_Xh);   cudaGetSymbolAddress((void**)&pXl, g_Xl);
    cudaGetSymbolAddress((void**)&pXth, g_Xth);
    cudaGetSymbolAddress((void**)&pAph, g_Aph);
    cudaGetSymbolAddress((void**)&pPt, g_Pt);
    cudaGetSymbolAddress((void**)&pAggh, g_aggh); cudaGetSymbolAddress((void**)&pAggl, g_aggl);
    cudaGetSymbolAddress((void**)&pWth, g_Wth); cudaGetSymbolAddress((void**)&pWtl, g_Wtl);
    cudaGetSymbolAddress((void**)&pWoth, g_Woth); cudaGetSymbolAddress((void**)&pWotl, g_Wotl);

    cudaFuncSetAttribute((const void*)k_gemm<3,3>, cudaFuncAttributeMaxDynamicSharedMemorySize, GEMM_SMEM);
    cudaFuncSetAttribute((const void*)k_gemm<2,3>, cudaFuncAttributeMaxDynamicSharedMemorySize, GEMM_SMEM);
    cudaFuncSetAttribute((const void*)k_gemm64<4,2,2,false>, cudaFuncAttributeMaxDynamicSharedMemorySize, S_SMEM);
    cudaFuncSetAttribute((const void*)k_gemm64<1,1,3,true>,  cudaFuncAttributeMaxDynamicSharedMemorySize, PV_SMEM);

    // 1) W = Wq Wk^T, u = Wk bq
    k_precomp<<<DD + 1, DD>>>(Wq, Wk, bq);
    // 2) all splits/transposes + c
    k_prep<<<6656, 256>>>(inp, Wo);
    // 3) A' = X @ W -> fp16 (hi only; 3 combos)
    k_gemm<3,3><<<dim3(ROWS/128, 2, 1), 256, GEMM_SMEM>>>(
        pXh, pXl, pWth, pWtl, nullptr, pAph, nullptr, DD, DD, 0);
    // 4) S GEMM fused with per-tile softmax: Pt + mt/st   [profiled slot]
    k_gemm64<4,2,2,false><<<dim3(NN/128, NN/128, BB), 256, S_SMEM>>>(
        pAph, pXh, pXl, pPt, nullptr, pCvec, nullptr, pMt, pSt,
        DD, NN, (size_t)NN*DD, (size_t)NN*DD, (size_t)NN*NN);
    // 5) per-row normalization -> Cfac
    k_norm<<<ROWS/256, 256>>>();
    // 6) agg = sum_kt Cfac*Pt @ Xth  (K=2048, 1 combo, 3-stage, A scaled) -> fp16 splits
    k_gemm64<1,1,3,true><<<dim3(NN/128, 2, BB), 256, PV_SMEM>>>(
        pPt, pXth, nullptr, pAggh, pAggl, nullptr, pCf, nullptr, nullptr,
        NN, DD, (size_t)NN*NN, (size_t)DD*NN, (size_t)NN*DD);
    // 7) out = relu(agg @ Wo + bo) -> fp32  (3 combos)
    k_gemm<2,3><<<dim3(ROWS/128, 2, 1), 256, GEMM_SMEM>>>(
        pAggh, pAggl, pWoth, pWotl, out, nullptr, bo, DD, DD, 0);
}

// round 14
// speedup vs baseline: 1.3972x; 1.0246x over previous
#include <cuda_runtime.h>
#include <cuda_fp16.h>
#include <cstdint>

#define DD 256
#define BB 16
#define NN 2048
#define ROWS (BB*NN)

typedef __half h16;

// ------------------------------------------------------------------ scratch
__device__ float g_W[DD*DD];                 // Wq @ Wk^T
__device__ float g_u[DD];                    // Wk @ bq
__device__ float g_c[ROWS];                  // X . u  (per key row)
__device__ float g_mt[(size_t)ROWS*16];      // per (row, ntile) max
__device__ float g_st[(size_t)ROWS*16];      // per (row, ntile) sum
__device__ float g_cf[(size_t)ROWS*16];      // per (row, ntile) exp(mt-m)/l

__device__ h16 g_Xh[(size_t)ROWS*DD],  g_Xl[(size_t)ROWS*DD];    // X splits (row-major)
__device__ h16 g_Xth[(size_t)BB*DD*NN];                          // X^T (hi only)
__device__ h16 g_Aph[(size_t)ROWS*DD];                           // A' = X@W (fp16)
__device__ h16 g_Pt[(size_t)ROWS*NN];                            // exp(s - m_tile) fp16
__device__ h16 g_aggh[(size_t)ROWS*DD], g_aggl[(size_t)ROWS*DD]; // agg splits
__device__ h16 g_Wth[DD*DD], g_Wtl[DD*DD];   // (WqWk^T)^T splits
__device__ h16 g_Woth[DD*DD], g_Wotl[DD*DD]; // Wo^T splits

// ------------------------------------------------------------------ helpers
__device__ __forceinline__ uint32_t smem_u32(const void* p) {
    uint32_t a;
    asm("{ .reg .u64 t; cvta.to.shared.u64 t, %1; cvt.u32.u64 %0, t; }" : "=r"(a) : "l"(p));
    return a;
}
#define CP16(dst, src) \
    asm volatile("cp.async.cg.shared.global [%0], [%1], 16;" :: "r"(dst), "l"(src))
#define CP_COMMIT() asm volatile("cp.async.commit_group;" ::: "memory")
#define CP_WAIT(n)  asm volatile("cp.async.wait_group %0;" :: "n"(n) : "memory")

#define MMA16816(c, a, b)                                                     \
    asm volatile("mma.sync.aligned.m16n8k16.row.col.f32.f16.f16.f32 "         \
        "{%0,%1,%2,%3},{%4,%5,%6,%7},{%8,%9},{%0,%1,%2,%3};"                  \
        : "+f"((c)[0]), "+f"((c)[1]), "+f"((c)[2]), "+f"((c)[3])              \
        : "r"((a)[0]), "r"((a)[1]), "r"((a)[2]), "r"((a)[3]),                 \
          "r"((b)[0]), "r"((b)[1]))

#define LDSM4(r0, r1, r2, r3, addr)                                           \
    asm volatile("ldmatrix.sync.aligned.m8n8.x4.shared.b16 {%0,%1,%2,%3}, [%4];" \
        : "=r"(r0), "=r"(r1), "=r"(r2), "=r"(r3) : "r"(addr))

__device__ __forceinline__ void split2(float f, h16& h, h16& l) {
    h = __float2half_rn(f);
    l = __float2half_rn(f - __half2float(h));
}

// ------------------------------------------------------------------ precompute: W = Wq@Wk^T, u = Wk@bq
__global__ void k_precomp(const float* __restrict__ Wq, const float* __restrict__ Wk,
                          const float* __restrict__ bq) {
    __shared__ float v[DD];
    int bx = blockIdx.x;
    if (bx < DD) {
        v[threadIdx.x] = Wq[bx*DD + threadIdx.x];
        __syncthreads();
        int j = threadIdx.x;
        const float* wk = Wk + j*DD;
        float s = 0.f;
#pragma unroll 8
        for (int e = 0; e < DD; e++) s += v[e] * wk[e];
        g_W[bx*DD + j] = s;
    } else {
        v[threadIdx.x] = bq[threadIdx.x];
        __syncthreads();
        int i = threadIdx.x;
        const float* wk = Wk + i*DD;
        float s = 0.f;
#pragma unroll 8
        for (int e = 0; e < DD; e++) s += wk[e] * v[e];
        g_u[i] = s;
    }
}

// ------------------------------------------------------------------ fused prep
__global__ __launch_bounds__(256) void k_prep(const float* __restrict__ X,
                                              const float* __restrict__ Wo) {
    __shared__ float t[64][65];
    __shared__ float us[DD];
    int bx = blockIdx.x, tid = threadIdx.x;
    if (bx < 512) {
        int which = bx >> 8, j = bx & 255, d = tid;
        const float* src = which ? Wo : g_W;
        h16* dh = which ? g_Woth : g_Wth;
        h16* dl = which ? g_Wotl : g_Wtl;
        float f = src[d*DD + j];
        split2(f, dh[j*DD + d], dl[j*DD + d]);
    } else if (bx < 4608) {
        if (tid < DD) us[tid] = g_u[tid];
        __syncthreads();
        int warp = (bx - 512)*8 + (tid >> 5);
        int lane = tid & 31;
        const float* x = X + (size_t)warp * DD;
        float c = 0.f;
#pragma unroll
        for (int i = 0; i < 8; i++) {
            int e = lane + 32*i;
            float f = x[e];
            c += f * us[e];
            split2(f, g_Xh[(size_t)warp*DD + e], g_Xl[(size_t)warp*DD + e]);
        }
#pragma unroll
        for (int o = 16; o; o >>= 1) c += __shfl_xor_sync(0xffffffffu, c, o);
        if (lane == 0) g_c[warp] = c;
    } else {
        int idx = bx - 4608;
        int n0 = (idx & 31) * 64, d0 = ((idx >> 5) & 3) * 64, b = idx >> 7;
        const float* Xb = X + (size_t)b * NN * DD;
        for (int u = tid; u < 64*16; u += 256) {
            int r = u >> 4, c4 = u & 15;
            float4 v = *(const float4*)(Xb + (size_t)(n0 + r)*DD + d0 + c4*4);
            t[r][c4*4+0] = v.x; t[r][c4*4+1] = v.y; t[r][c4*4+2] = v.z; t[r][c4*4+3] = v.w;
        }
        __syncthreads();
        size_t ob = (size_t)b * DD * NN;
        for (int u = tid; u < 4096; u += 256) {
            int r = u >> 6, c = u & 63;
            g_Xth[ob + (size_t)(d0 + r)*NN + n0 + c] = __float2half_rn(t[c][r]);
        }
    }
}

// per-row normalization: m = max mt, l = sum st*exp(mt-m), cf = exp(mt-m)/l
__global__ __launch_bounds__(256) void k_norm() {
    int r = blockIdx.x * 256 + threadIdx.x;
    float mt[16], m = -1e30f;
#pragma unroll
    for (int q = 0; q < 16; q++) {
        mt[q] = g_mt[(size_t)r*16 + q];
        m = fmaxf(m, mt[q]);
    }
    float e[16], l = 0.f;
#pragma unroll
    for (int q = 0; q < 16; q++) {
        e[q] = __expf(mt[q] - m);
        l += g_st[(size_t)r*16 + q] * e[q];
    }
    float inv = 1.f / l;
#pragma unroll
    for (int q = 0; q < 16; q++)
        g_cf[(size_t)r*16 + q] = e[q] * inv;
}

// ------------------------------------------------------------------ HMMA GEMM (32-K chunks, small 3-combo GEMMs)
#define TPAD   40
#define TILE_B (128*TPAD*2)       // 10240
#define OFF_AH 0
#define OFF_AL (1*TILE_B)
#define OFF_BH (2*TILE_B)
#define OFF_BL (3*TILE_B)
#define STAGE_B (4*TILE_B)        // 40960
#define GEMM_SMEM (2*STAGE_B)     // 81920

// EPI: 2 = bias+relu fp32   3 = fp16 hi-only
template<int EPI, int COMBOS>
__global__ __launch_bounds__(256, 2) void k_gemm(
    const h16* __restrict__ Ah, const h16* __restrict__ Al,
    const h16* __restrict__ Bh, const h16* __restrict__ Bl,
    float* __restrict__ Cf, h16* __restrict__ Ch,
    const float* __restrict__ bias,
    int K, int ldc, size_t sC)
{
    extern __shared__ char smem[];
    uint32_t sb = smem_u32(smem);
    int tid = threadIdx.x;
    int lane = tid & 31, wid = tid >> 5;
    int g = lane >> 2, t = lane & 3;
    int warp_m = (wid & 1) * 64;
    int warp_n = (wid >> 1) * 32;
    int m0 = blockIdx.x * 128, n0 = blockIdx.y * 128, b = blockIdx.z;

    size_t go0 = (size_t)(tid >> 2) * K + (tid & 3) * 8;
    size_t go1 = go0 + (size_t)64 * K;
    uint32_t do0 = (uint32_t)((tid >> 2) * 80 + (tid & 3) * 16);
    uint32_t do1 = do0 + 64*80;

    int lr = ((lane >> 3) & 1) * 8 + (lane & 7);
    int lk = (lane >> 4) * 16;
    uint32_t a_off[4], b_off[2];
#pragma unroll
    for (int i = 0; i < 4; i++) a_off[i] = (uint32_t)((warp_m + i*16 + lr)*80 + lk);
#pragma unroll
    for (int p = 0; p < 2; p++) b_off[p] = (uint32_t)((warp_n + p*16 + lr)*80 + lk);

    const h16* pAh = Ah + (size_t)m0*K;
    const h16* pAl = (COMBOS >= 3) ? Al + (size_t)m0*K : nullptr;
    const h16* pBh = Bh + (size_t)n0*K;
    const h16* pBl = (COMBOS >= 2) ? Bl + (size_t)n0*K : nullptr;

    float acc[4][4][4];
#pragma unroll
    for (int i = 0; i < 4; i++)
#pragma unroll
        for (int j = 0; j < 4; j++)
#pragma unroll
            for (int r = 0; r < 4; r++) acc[i][j][r] = 0.f;

#define ISSUE_CHUNK(sbase, k0) do {                                          \
        CP16((sbase) + OFF_AH + do0, pAh + go0 + (k0));                      \
        CP16((sbase) + OFF_AH + do1, pAh + go1 + (k0));                      \
        if (COMBOS >= 3) {                                                   \
            CP16((sbase) + OFF_AL + do0, pAl + go0 + (k0));                  \
            CP16((sbase) + OFF_AL + do1, pAl + go1 + (k0));                  \
        }                                                                    \
        CP16((sbase) + OFF_BH + do0, pBh + go0 + (k0));                      \
        CP16((sbase) + OFF_BH + do1, pBh + go1 + (k0));                      \
        if (COMBOS >= 2) {                                                   \
            CP16((sbase) + OFF_BL + do0, pBl + go0 + (k0));                  \
            CP16((sbase) + OFF_BL + do1, pBl + go1 + (k0));                  \
        }                                                                    \
    } while (0)

    int nchunk = K >> 5;
    ISSUE_CHUNK(sb, 0);
    CP_COMMIT();

    for (int ch = 0; ch < nchunk; ch++) {
        int st = ch & 1;
        if (ch + 1 < nchunk) {
            ISSUE_CHUNK(sb + (uint32_t)(st ^ 1)*STAGE_B, (ch+1) << 5);
            CP_COMMIT();
            CP_WAIT(1);
        } else {
            CP_WAIT(0);
        }
        __syncthreads();

        uint32_t base = sb + (uint32_t)st * STAGE_B;
#pragma unroll
        for (int ks = 0; ks < 2; ks++) {
            uint32_t kb = ks * 32;
            uint32_t ah[4][4], al[4][4], bh[4][2], bl[4][2];
#pragma unroll
            for (int i = 0; i < 4; i++) {
                LDSM4(ah[i][0], ah[i][1], ah[i][2], ah[i][3], base + OFF_AH + a_off[i] + kb);
                if (COMBOS >= 3)
                    LDSM4(al[i][0], al[i][1], al[i][2], al[i][3], base + OFF_AL + a_off[i] + kb);
            }
#pragma unroll
            for (int p = 0; p < 2; p++) {
                LDSM4(bh[2*p][0], bh[2*p+1][0], bh[2*p][1], bh[2*p+1][1],
                      base + OFF_BH + b_off[p] + kb);
                if (COMBOS >= 2)
                    LDSM4(bl[2*p][0], bl[2*p+1][0], bl[2*p][1], bl[2*p+1][1],
                          base + OFF_BL + b_off[p] + kb);
            }
#pragma unroll
            for (int i = 0; i < 4; i++)
#pragma unroll
                for (int j = 0; j < 4; j++) {
                    MMA16816(acc[i][j], ah[i], bh[j]);
                    if (COMBOS >= 2) MMA16816(acc[i][j], ah[i], bl[j]);
                    if (COMBOS >= 3) MMA16816(acc[i][j], al[i], bh[j]);
                }
        }
        __syncthreads();
    }

#pragma unroll
    for (int i = 0; i < 4; i++) {
        int row0 = m0 + warp_m + i*16 + g;
#pragma unroll
        for (int j = 0; j < 4; j++) {
            int col = n0 + warp_n + j*8 + 2*t;
            if (EPI == 3) {
                size_t o0 = (size_t)row0*ldc + col;
                size_t o1 = o0 + 8*(size_t)ldc;
                *(__half2*)(Ch + o0) = __floats2half2_rn(acc[i][j][0], acc[i][j][1]);
                *(__half2*)(Ch + o1) = __floats2half2_rn(acc[i][j][2], acc[i][j][3]);
            } else {
                float b0 = bias[col], b1 = bias[col+1];
                float* d0 = Cf + (size_t)row0*ldc + col;
                float* d1 = d0 + 8*ldc;
                *(float2*)d0 = make_float2(fmaxf(acc[i][j][0]+b0, 0.f),
                                           fmaxf(acc[i][j][1]+b1, 0.f));
                *(float2*)d1 = make_float2(fmaxf(acc[i][j][2]+b0, 0.f),
                                           fmaxf(acc[i][j][3]+b1, 0.f));
            }
        }
    }
#undef ISSUE_CHUNK
}

// ------------------------------------------------------------------ HMMA GEMM, 64-K chunks, 1 barrier/chunk
// EPI: 1 = fp16 hi/lo split   4 = exp-tile (fused softmax pieces)
// SCA: scale A fragments by per-(row, ktile) Cfac (PV normalization).
#define T64_B  (128*144)

template<int EPI, int COMBOS, int NSTAGE, bool SCA>
__global__ __launch_bounds__(256, 2) void k_gemm64(
    const h16* __restrict__ Ah,
    const h16* __restrict__ Bh, const h16* __restrict__ Bl,
    h16* __restrict__ Ch, h16* __restrict__ Cl,
    const float* __restrict__ bias, const float* __restrict__ Cfac,
    float* __restrict__ Mt, float* __restrict__ St,
    int K, int ldc, size_t sA, size_t sB, size_t sC)
{
    constexpr uint32_t OFF_A = 0;
    constexpr uint32_t OFF_B = T64_B;
    constexpr uint32_t OFF_B2 = 2*T64_B;
    constexpr uint32_t STAGE = (COMBOS >= 2 ? 3 : 2) * T64_B;

    extern __shared__ char smem[];
    uint32_t sb = smem_u32(smem);
    int tid = threadIdx.x;
    int lane = tid & 31, wid = tid >> 5;
    int g = lane >> 2, t = lane & 3;
    int warp_m = (wid & 1) * 64;
    int warp_n = (wid >> 1) * 32;
    int m0 = blockIdx.x * 128, n0 = blockIdx.y * 128, b = blockIdx.z;

    size_t gob = (size_t)(tid >> 3) * K + (tid & 7) * 8;
    uint32_t dob = (uint32_t)((tid >> 3) * 144 + (tid & 7) * 16);

    int lr = ((lane >> 3) & 1) * 8 + (lane & 7);
    int lk = (lane >> 4) * 16;
    uint32_t a_off[4], b_off[2];
#pragma unroll
    for (int i = 0; i < 4; i++) a_off[i] = (uint32_t)((warp_m + i*16 + lr)*144 + lk);
#pragma unroll
    for (int p = 0; p < 2; p++) b_off[p] = (uint32_t)((warp_n + p*16 + lr)*144 + lk);

    const h16* pAh = Ah + (size_t)b*sA + (size_t)m0*K;
    const h16* pBh = Bh + (size_t)b*sB + (size_t)n0*K;
    const h16* pBl = (COMBOS >= 2) ? Bl + (size_t)b*sB + (size_t)n0*K : nullptr;

    float acc[4][4][4];
#pragma unroll
    for (int i = 0; i < 4; i++)
#pragma unroll
        for (int j = 0; j < 4; j++)
#pragma unroll
            for (int r = 0; r < 4; r++) acc[i][j][r] = 0.f;

    __half2 hA[4], hB[4];

#define ISSUE64(sbase, k0) do {                                              \
        _Pragma("unroll")                                                    \
        for (int _i = 0; _i < 4; _i++) {                                     \
            size_t _g = gob + (size_t)(32*_i)*K + (k0);                      \
            uint32_t _d = dob + 32*_i*144;                                   \
            CP16((sbase) + OFF_A + _d, pAh + _g);                            \
            CP16((sbase) + OFF_B + _d, pBh + _g);                            \
            if (COMBOS >= 2) CP16((sbase) + OFF_B2 + _d, pBl + _g);          \
        }                                                                    \
    } while (0)

#define COMPUTE64(basev) do {                                                \
        _Pragma("unroll")                                                    \
        for (int ks = 0; ks < 4; ks++) {                                     \
            uint32_t kb = ks * 32;                                           \
            uint32_t ah[4][4], bh[4][2], bl[4][2];                           \
            _Pragma("unroll")                                                \
            for (int i = 0; i < 4; i++) {                                    \
                LDSM4(ah[i][0], ah[i][1], ah[i][2], ah[i][3],                \
                      (basev) + OFF_A + a_off[i] + kb);                      \
                if (SCA) {                                                   \
                    *(__half2*)&ah[i][0] = __hmul2(*(__half2*)&ah[i][0], hA[i]); \
                    *(__half2*)&ah[i][1] = __hmul2(*(__half2*)&ah[i][1], hB[i]); \
                    *(__half2*)&ah[i][2] = __hmul2(*(__half2*)&ah[i][2], hA[i]); \
                    *(__half2*)&ah[i][3] = __hmul2(*(__half2*)&ah[i][3], hB[i]); \
                }                                                            \
            }                                                                \
            _Pragma("unroll")                                                \
            for (int p = 0; p < 2; p++) {                                    \
                LDSM4(bh[2*p][0], bh[2*p+1][0], bh[2*p][1], bh[2*p+1][1],    \
                      (basev) + OFF_B + b_off[p] + kb);                      \
                if (COMBOS >= 2)                                             \
                    LDSM4(bl[2*p][0], bl[2*p+1][0], bl[2*p][1], bl[2*p+1][1],\
                          (basev) + OFF_B2 + b_off[p] + kb);                 \
            }                                                                \
            _Pragma("unroll")                                                \
            for (int i = 0; i < 4; i++)                                      \
                _Pragma("unroll")                                            \
                for (int j = 0; j < 4; j++) {                                \
                    MMA16816(acc[i][j], ah[i], bh[j]);                       \
                    if (COMBOS >= 2) MMA16816(acc[i][j], ah[i], bl[j]);      \
                }                                                            \
        }                                                                    \
    } while (0)

#define LOAD_CF(ch) do {                                                     \
        if (SCA && ((ch) & 1) == 0) {                                        \
            int kt = (ch) >> 1;                                              \
            _Pragma("unroll")                                                \
            for (int i = 0; i < 4; i++) {                                    \
                float fA = Cfac[((size_t)b*NN + m0 + warp_m + i*16 + g)*16 + kt];     \
                float fB = Cfac[((size_t)b*NN + m0 + warp_m + i*16 + g + 8)*16 + kt]; \
                hA[i] = __half2half2(__float2half_rn(fA));                   \
                hB[i] = __half2half2(__float2half_rn(fB));                   \
            }                                                                \
        }                                                                    \
    } while (0)

    int nchunk = K >> 6;
    if (NSTAGE == 2) {
        ISSUE64(sb, 0);
        CP_COMMIT();
        for (int ch = 0; ch < nchunk; ch++) {
            CP_WAIT(0);
            __syncthreads();
            uint32_t base = sb + (uint32_t)(ch & 1) * STAGE;
            if (ch + 1 < nchunk) {
                ISSUE64(sb + (uint32_t)((ch + 1) & 1) * STAGE, (ch+1) << 6);
                CP_COMMIT();
            }
            LOAD_CF(ch);
            COMPUTE64(base);
        }
    } else {
        ISSUE64(sb, 0);
        CP_COMMIT();
        if (nchunk > 1) ISSUE64(sb + STAGE, 64);
        CP_COMMIT();
        int st = 0;
        for (int ch = 0; ch < nchunk; ch++) {
            CP_WAIT(1);
            __syncthreads();
            uint32_t base = sb + (uint32_t)st * STAGE;
            int st2 = st + 2; if (st2 >= 3) st2 -= 3;
            if (ch + 2 < nchunk) ISSUE64(sb + (uint32_t)st2 * STAGE, (ch+2) << 6);
            CP_COMMIT();
            LOAD_CF(ch);
            COMPUTE64(base);
            st++; if (st == 3) st = 0;
        }
    }

    // ---- epilogue ----
    if (EPI == 4) {
        // fused: c-add, per-tile row max, exp (MUFU), fp16 store, row sums, mt/st out
        __syncthreads();                  // mainloop smem done; reuse for reductions
        float* red   = (float*)smem;      // [128][4]
        float* bcast = red + 512;         // [128]
        float* sred  = bcast + 128;       // [128][4]
        int ntile = blockIdx.y;

        // hoisted per-column c
        float cj0[4], cj1[4];
#pragma unroll
        for (int j = 0; j < 4; j++) {
            int col = n0 + warp_n + j*8 + 2*t;
            cj0[j] = bias[(size_t)b*ldc + col];
            cj1[j] = bias[(size_t)b*ldc + col + 1];
        }

        float mA[4], mB[4];
#pragma unroll
        for (int i = 0; i < 4; i++) {
            mA[i] = -1e30f; mB[i] = -1e30f;
#pragma unroll
            for (int j = 0; j < 4; j++) {
                acc[i][j][0] += cj0[j]; acc[i][j][1] += cj1[j];
                acc[i][j][2] += cj0[j]; acc[i][j][3] += cj1[j];
                mA[i] = fmaxf(mA[i], fmaxf(acc[i][j][0], acc[i][j][1]));
                mB[i] = fmaxf(mB[i], fmaxf(acc[i][j][2], acc[i][j][3]));
            }
            mA[i] = fmaxf(mA[i], __shfl_xor_sync(0xffffffffu, mA[i], 1));
            mA[i] = fmaxf(mA[i], __shfl_xor_sync(0xffffffffu, mA[i], 2));
            mB[i] = fmaxf(mB[i], __shfl_xor_sync(0xffffffffu, mB[i], 1));
            mB[i] = fmaxf(mB[i], __shfl_xor_sync(0xffffffffu, mB[i], 2));
        }
        if (t == 0) {
#pragma unroll
            for (int i = 0; i < 4; i++) {
                red[(warp_m + i*16 + g)*4 + (wid >> 1)]     = mA[i];
                red[(warp_m + i*16 + g + 8)*4 + (wid >> 1)] = mB[i];
            }
        }
        __syncthreads();
        if (tid < 128)
            bcast[tid] = fmaxf(fmaxf(red[tid*4], red[tid*4+1]),
                               fmaxf(red[tid*4+2], red[tid*4+3]));
        __syncthreads();
#pragma unroll
        for (int i = 0; i < 4; i++) {
            int rA = warp_m + i*16 + g, rB = rA + 8;
            float emA = bcast[rA], emB = bcast[rB];
            float sA = 0.f, sB = 0.f;
            size_t oA = (size_t)b*sC + (size_t)(m0 + rA)*ldc + n0;
            size_t oB = oA + 8*(size_t)ldc;
#pragma unroll
            for (int j = 0; j < 4; j++) {
                int cl = warp_n + j*8 + 2*t;
                float p0 = __expf(acc[i][j][0] - emA), p1 = __expf(acc[i][j][1] - emA);
                float p2 = __expf(acc[i][j][2] - emB), p3 = __expf(acc[i][j][3] - emB);
                sA += p0 + p1; sB += p2 + p3;
                *(__half2*)(Ch + oA + cl) = __floats2half2_rn(p0, p1);
                *(__half2*)(Ch + oB + cl) = __floats2half2_rn(p2, p3);
            }
            sA += __shfl_xor_sync(0xffffffffu, sA, 1);
            sA += __shfl_xor_sync(0xffffffffu, sA, 2);
            sB += __shfl_xor_sync(0xffffffffu, sB, 1);
            sB += __shfl_xor_sync(0xffffffffu, sB, 2);
            if (t == 0) {
                sred[rA*4 + (wid >> 1)] = sA;
                sred[rB*4 + (wid >> 1)] = sB;
            }
        }
        __syncthreads();
        if (tid < 128) {
            size_t o = ((size_t)b*NN + m0 + tid)*16 + ntile;
            Mt[o] = bcast[tid];
            St[o] = sred[tid*4] + sred[tid*4+1] + sred[tid*4+2] + sred[tid*4+3];
        }
    } else {
#pragma unroll
        for (int i = 0; i < 4; i++) {
            int row0 = m0 + warp_m + i*16 + g;
#pragma unroll
            for (int j = 0; j < 4; j++) {
                int col = n0 + warp_n + j*8 + 2*t;
                float v0 = acc[i][j][0], v1 = acc[i][j][1];
                float v2 = acc[i][j][2], v3 = acc[i][j][3];
                h16 h0, l0, h1, l1, h2, l2, h3, l3;
                split2(v0, h0, l0); split2(v1, h1, l1);
                split2(v2, h2, l2); split2(v3, h3, l3);
                size_t o0 = (size_t)b*sC + (size_t)row0*ldc + col;
                size_t o1 = o0 + 8*(size_t)ldc;
                *(__half2*)(Ch + o0) = __halves2half2(h0, h1);
                *(__half2*)(Ch + o1) = __halves2half2(h2, h3);
                *(__half2*)(Cl + o0) = __halves2half2(l0, l1);
                *(__half2*)(Cl + o1) = __halves2half2(l2, l3);
            }
        }
    }
#undef ISSUE64
#undef COMPUTE64
#undef LOAD_CF
}

#define S_SMEM   (2*3*T64_B)   // 110592 (2 stages x 3 tiles)
#define PV_SMEM  (3*2*T64_B)   // 110592 (3 stages x 2 tiles)

// ------------------------------------------------------------------ launch
extern "C" void kernel_launch(void* const* d_in, const int* in_sizes, int n_in,
                              void* d_out, int out_size) {
    const float* inp = (const float*)d_in[0];
    const float* Wq  = (const float*)d_in[1];
    const float* bq  = (const float*)d_in[2];
    const float* Wk  = (const float*)d_in[3];
    // bk (d_in[4]) provably drops out of the softmax — unused.
    const float* Wo  = (const float*)d_in[5];
    const float* bo  = (const float*)d_in[6];
    float* out = (float*)d_out;

    float *pCvec, *pMt, *pSt, *pCf;
    h16 *pXh, *pXl, *pXth, *pAph, *pPt, *pAggh, *pAggl;
    h16 *pWth, *pWtl, *pWoth, *pWotl;
    cudaGetSymbolAddress((void**)&pCvec, g_c);
    cudaGetSymbolAddress((void**)&pMt, g_mt);
    cudaGetSymbolAddress((void**)&pSt, g_st);
    cudaGetSymbolAddress((void**)&pCf, g_cf);
    cudaGetSymbolAddress((void**)&pXh, g_Xh);   cudaGetSymbolAddress((void**)&pXl, g_Xl);
    cudaGetSymbolAddress((void**)&pXth, g_Xth);
    cudaGetSymbolAddress((void**)&pAph, g_Aph);
    cudaGetSymbolAddress((void**)&pPt, g_Pt);
    cudaGetSymbolAddress((void**)&pAggh, g_aggh); cudaGetSymbolAddress((void**)&pAggl, g_aggl);
    cudaGetSymbolAddress((void**)&pWth, g_Wth); cudaGetSymbolAddress((void**)&pWtl, g_Wtl);
    cudaGetSymbolAddress((void**)&pWoth, g_Woth); cudaGetSymbolAddress((void**)&pWotl, g_Wotl);

    cudaFuncSetAttribute((const void*)k_gemm<3,3>, cudaFuncAttributeMaxDynamicSharedMemorySize, GEMM_SMEM);
    cudaFuncSetAttribute((const void*)k_gemm<2,3>, cudaFuncAttributeMaxDynamicSharedMemorySize, GEMM_SMEM);
    cudaFuncSetAttribute((const void*)k_gemm64<4,2,2,false>, cudaFuncAttributeMaxDynamicSharedMemorySize, S_SMEM);
    cudaFuncSetAttribute((const void*)k_gemm64<1,1,3,true>,  cudaFuncAttributeMaxDynamicSharedMemorySize, PV_SMEM);

    // 1) W = Wq Wk^T, u = Wk bq
    k_precomp<<<DD + 1, DD>>>(Wq, Wk, bq);
    // 2) all splits/transposes + c
    k_prep<<<6656, 256>>>(inp, Wo);
    // 3) A' = X @ W -> fp16 (hi only; 3 combos)
    k_gemm<3,3><<<dim3(ROWS/128, 2, 1), 256, GEMM_SMEM>>>(
        pXh, pXl, pWth, pWtl, nullptr, pAph, nullptr, DD, DD, 0);
    // 4) S GEMM fused with per-tile softmax: Pt + mt/st   [profiled slot]
    k_gemm64<4,2,2,false><<<dim3(NN/128, NN/128, BB), 256, S_SMEM>>>(
        pAph, pXh, pXl, pPt, nullptr, pCvec, nullptr, pMt, pSt,
        DD, NN, (size_t)NN*DD, (size_t)NN*DD, (size_t)NN*NN);
    // 5) per-row normalization -> Cfac
    k_norm<<<ROWS/256, 256>>>();
    // 6) agg = sum_kt Cfac*Pt @ Xth  (K=2048, 1 combo, 3-stage, A scaled) -> fp16 splits
    k_gemm64<1,1,3,true><<<dim3(NN/128, 2, BB), 256, PV_SMEM>>>(
        pPt, pXth, nullptr, pAggh, pAggl, nullptr, pCf, nullptr, nullptr,
        NN, DD, (size_t)NN*NN, (size_t)DD*NN, (size_t)NN*DD);
    // 7) out = relu(agg @ Wo + bo) -> fp32  (3 combos)
    k_gemm<2,3><<<dim3(ROWS/128, 2, 1), 256, GEMM_SMEM>>>(
        pAggh, pAggl, pWoth, pWotl, out, nullptr, bo, DD, DD, 0);
}